// round 1
// baseline (speedup 1.0000x reference)
#include <cuda_runtime.h>
#include <math.h>

#define BB 8
#define CC 512
#define LLEN 2048
#define NGRP 8
#define CPG 64        // channels per group
#define CL (CC*LLEN)  // per-batch channel-plane elements

// ---------------- scratch (no allocs allowed) ----------------
__device__ float g_h [BB*CC*LLEN];                 // normalized input
__device__ float g_q [BB*CC*LLEN];
__device__ float g_k [BB*CC*LLEN];
__device__ float g_v [BB*CC*LLEN];
__device__ float g_s [(size_t)BB*LLEN*LLEN];       // attention scores (134 MB)
__device__ float g_h2[BB*CC*LLEN];                 // attention output

// ---------------- GroupNorm ----------------
// one block per (batch, group); 512 threads; two passes (data fits L2 so re-read is cheap)
__global__ void gn_kernel(const float* __restrict__ x,
                          const float* __restrict__ gamma,
                          const float* __restrict__ beta,
                          float* __restrict__ h)
{
    int b = blockIdx.x / NGRP;
    int g = blockIdx.x % NGRP;
    const size_t base = ((size_t)b*CC + (size_t)g*CPG) * LLEN;
    const float* xp = x + base;
    float* hp = h + base;
    const int n = CPG * LLEN;  // 131072

    float s = 0.f, ss = 0.f;
    for (int i = threadIdx.x; i < n; i += blockDim.x) {
        float v = xp[i];
        s += v; ss += v*v;
    }
    __shared__ float rs[16], rss[16];
    #pragma unroll
    for (int o = 16; o; o >>= 1) {
        s  += __shfl_xor_sync(0xffffffffu, s,  o);
        ss += __shfl_xor_sync(0xffffffffu, ss, o);
    }
    int w = threadIdx.x >> 5;
    if ((threadIdx.x & 31) == 0) { rs[w] = s; rss[w] = ss; }
    __syncthreads();
    float tot = 0.f, tot2 = 0.f;
    int nw = blockDim.x >> 5;
    #pragma unroll
    for (int i = 0; i < 16; i++) {
        if (i < nw) { tot += rs[i]; tot2 += rss[i]; }
    }
    float mean = tot / (float)n;
    float var  = tot2 / (float)n - mean*mean;
    float inv  = rsqrtf(var + 1e-6f);

    for (int i = threadIdx.x; i < n; i += blockDim.x) {
        int c = g*CPG + i / LLEN;
        hp[i] = (xp[i] - mean) * inv * gamma[c] + beta[c];
    }
}

// ---------------- generic tiled fp32 GEMM ----------------
// C[b][m][n] = scale * sum_k A[m][k]*B[k][n]  (+ bias[m]) (+ resid[b][m][n])
// AT=0: A[m][k] = A[m*lda+k]   (K contiguous)
// AT=1: A[m][k] = A[k*lda+m]   (M contiguous)
// BT=0: B[k][n] = B[k*ldb+n]   (N contiguous)
// BT=1: B[k][n] = B[n*ldb+k]   (K contiguous)
// All of M,N multiples of 128; K multiple of 16. ldc = N.
template<int AT, int BT>
__global__ void __launch_bounds__(256)
gemm_kernel(const float* __restrict__ A, const float* __restrict__ B,
            float* __restrict__ C,
            int M, int N, int K, int lda, int ldb,
            long sA, long sB, long sC,
            const float* __restrict__ bias,
            const float* __restrict__ resid, long sR,
            float scale)
{
    const int BM = 128, BN = 128, BK = 16, LDS = 132; // padded smem stride
    __shared__ float As[BK*LDS];
    __shared__ float Bs[BK*LDS];

    int bz = blockIdx.z;
    A += (size_t)bz * sA;
    B += (size_t)bz * sB;
    C += (size_t)bz * sC;
    const float* R = resid ? resid + (size_t)bz * sR : nullptr;

    int m0 = blockIdx.y * BM;
    int n0 = blockIdx.x * BN;
    int tid = threadIdx.x;
    int tx = tid & 15;      // 0..15 -> n
    int ty = tid >> 4;      // 0..15 -> m

    float acc[8][8];
    #pragma unroll
    for (int i = 0; i < 8; i++)
        #pragma unroll
        for (int j = 0; j < 8; j++) acc[i][j] = 0.f;

    for (int k0 = 0; k0 < K; k0 += BK) {
        // ---- load A tile into As[k][m] ----
        if (AT == 0) {
            int m  = tid >> 2;           // 0..63
            int kv = (tid & 3) * 4;      // 0,4,8,12
            #pragma unroll
            for (int r = 0; r < 2; r++) {
                const float4 t = *(const float4*)&A[(size_t)(m0 + m + r*64)*lda + k0 + kv];
                As[(kv+0)*LDS + m + r*64] = t.x;
                As[(kv+1)*LDS + m + r*64] = t.y;
                As[(kv+2)*LDS + m + r*64] = t.z;
                As[(kv+3)*LDS + m + r*64] = t.w;
            }
        } else {
            int k  = tid >> 5;           // 0..7
            int mv = (tid & 31) * 4;     // 0..124
            #pragma unroll
            for (int r = 0; r < 2; r++) {
                const float4 t = *(const float4*)&A[(size_t)(k0 + k + r*8)*lda + m0 + mv];
                *(float4*)&As[(k + r*8)*LDS + mv] = t;
            }
        }
        // ---- load B tile into Bs[k][n] ----
        if (BT == 0) {
            int k  = tid >> 5;
            int nv = (tid & 31) * 4;
            #pragma unroll
            for (int r = 0; r < 2; r++) {
                const float4 t = *(const float4*)&B[(size_t)(k0 + k + r*8)*ldb + n0 + nv];
                *(float4*)&Bs[(k + r*8)*LDS + nv] = t;
            }
        } else {
            int nn = tid >> 2;
            int kv = (tid & 3) * 4;
            #pragma unroll
            for (int r = 0; r < 2; r++) {
                const float4 t = *(const float4*)&B[(size_t)(n0 + nn + r*64)*ldb + k0 + kv];
                Bs[(kv+0)*LDS + nn + r*64] = t.x;
                Bs[(kv+1)*LDS + nn + r*64] = t.y;
                Bs[(kv+2)*LDS + nn + r*64] = t.z;
                Bs[(kv+3)*LDS + nn + r*64] = t.w;
            }
        }
        __syncthreads();

        #pragma unroll
        for (int kk = 0; kk < BK; kk++) {
            float af[8], bf[8];
            *(float4*)&af[0] = *(const float4*)&As[kk*LDS + ty*8];
            *(float4*)&af[4] = *(const float4*)&As[kk*LDS + ty*8 + 4];
            *(float4*)&bf[0] = *(const float4*)&Bs[kk*LDS + tx*8];
            *(float4*)&bf[4] = *(const float4*)&Bs[kk*LDS + tx*8 + 4];
            #pragma unroll
            for (int i = 0; i < 8; i++)
                #pragma unroll
                for (int j = 0; j < 8; j++)
                    acc[i][j] += af[i] * bf[j];
        }
        __syncthreads();
    }

    // ---- epilogue ----
    #pragma unroll
    for (int i = 0; i < 8; i++) {
        int m = m0 + ty*8 + i;
        float bi = bias ? bias[m] : 0.f;
        #pragma unroll
        for (int j = 0; j < 8; j++) {
            int n = n0 + tx*8 + j;
            float v = acc[i][j] * scale + bi;
            if (R) v += R[(size_t)m * N + n];
            C[(size_t)m * N + n] = v;
        }
    }
}

// ---------------- row softmax (in place) ----------------
// one block (256 threads) per row of 2048
__global__ void softmax_kernel(float* __restrict__ S)
{
    float* row = S + (size_t)blockIdx.x * LLEN;
    int tid = threadIdx.x;
    float v[8];
    float mx = -1e30f;
    #pragma unroll
    for (int i = 0; i < 8; i++) {
        v[i] = row[tid + 256*i];
        mx = fmaxf(mx, v[i]);
    }
    __shared__ float rmax[8], rsum[8];
    #pragma unroll
    for (int o = 16; o; o >>= 1) mx = fmaxf(mx, __shfl_xor_sync(0xffffffffu, mx, o));
    if ((tid & 31) == 0) rmax[tid >> 5] = mx;
    __syncthreads();
    float m = rmax[0];
    #pragma unroll
    for (int i = 1; i < 8; i++) m = fmaxf(m, rmax[i]);

    float sm = 0.f;
    #pragma unroll
    for (int i = 0; i < 8; i++) { v[i] = __expf(v[i] - m); sm += v[i]; }
    #pragma unroll
    for (int o = 16; o; o >>= 1) sm += __shfl_xor_sync(0xffffffffu, sm, o);
    if ((tid & 31) == 0) rsum[tid >> 5] = sm;
    __syncthreads();
    float tot = 0.f;
    #pragma unroll
    for (int i = 0; i < 8; i++) tot += rsum[i];
    float inv = 1.f / tot;
    #pragma unroll
    for (int i = 0; i < 8; i++) row[tid + 256*i] = v[i] * inv;
}

// ---------------- launch ----------------
extern "C" void kernel_launch(void* const* d_in, const int* in_sizes, int n_in,
                              void* d_out, int out_size)
{
    const float* x     = (const float*)d_in[0];
    const float* gamma = (const float*)d_in[1];
    const float* beta  = (const float*)d_in[2];
    const float* wq    = (const float*)d_in[3];
    const float* bq    = (const float*)d_in[4];
    const float* wk    = (const float*)d_in[5];
    const float* bk    = (const float*)d_in[6];
    const float* wv    = (const float*)d_in[7];
    const float* bv    = (const float*)d_in[8];
    const float* wo    = (const float*)d_in[9];
    const float* bo    = (const float*)d_in[10];
    float* out = (float*)d_out;

    float *h, *q, *k, *v, *s, *h2;
    cudaGetSymbolAddress((void**)&h,  g_h);
    cudaGetSymbolAddress((void**)&q,  g_q);
    cudaGetSymbolAddress((void**)&k,  g_k);
    cudaGetSymbolAddress((void**)&v,  g_v);
    cudaGetSymbolAddress((void**)&s,  g_s);
    cudaGetSymbolAddress((void**)&h2, g_h2);

    const long sLL = (long)LLEN * LLEN;
    const float scl = 1.0f / sqrtf((float)CC);

    gn_kernel<<<BB*NGRP, 512>>>(x, gamma, beta, h);

    dim3 blk(256);
    dim3 gProj(LLEN/128, CC/128, BB);      // (16, 4, 8)
    dim3 gAttn(LLEN/128, LLEN/128, BB);    // (16, 16, 8)

    // q/k/v = W @ h + b       (A: W row-major [C,C]; B: h [C,L] per batch)
    gemm_kernel<0,0><<<gProj, blk>>>(wq, h, q, CC, LLEN, CC, CC, LLEN,
                                     0L, (long)CL, (long)CL, bq, nullptr, 0L, 1.f);
    gemm_kernel<0,0><<<gProj, blk>>>(wk, h, k, CC, LLEN, CC, CC, LLEN,
                                     0L, (long)CL, (long)CL, bk, nullptr, 0L, 1.f);
    gemm_kernel<0,0><<<gProj, blk>>>(wv, h, v, CC, LLEN, CC, CC, LLEN,
                                     0L, (long)CL, (long)CL, bv, nullptr, 0L, 1.f);

    // scores = scale * q^T k   (M=N=L, K=C)
    gemm_kernel<1,0><<<gAttn, blk>>>(q, k, s, LLEN, LLEN, CC, LLEN, LLEN,
                                     (long)CL, (long)CL, sLL, nullptr, nullptr, 0L, scl);

    softmax_kernel<<<BB*LLEN, 256>>>(s);

    // h2[c][i] = sum_j v[c][j] * s[i][j]   (M=C, N=L, K=L)
    gemm_kernel<0,1><<<gProj, blk>>>(v, s, h2, CC, LLEN, LLEN, LLEN, LLEN,
                                     (long)CL, sLL, (long)CL, nullptr, nullptr, 0L, 1.f);

    // out = x + Wo @ h2 + bo
    gemm_kernel<0,0><<<gProj, blk>>>(wo, h2, out, CC, LLEN, CC, CC, LLEN,
                                     0L, (long)CL, (long)CL, bo, x, (long)CL, 1.f);
}

// round 3
// speedup vs baseline: 2.4667x; 2.4667x over previous
#include <cuda_runtime.h>
#include <cuda_bf16.h>
#include <cstdint>
#include <math.h>

#define BB 8
#define CC 512
#define LLEN 2048
#define NGRP 8
#define CPG 64
#define CL (CC*LLEN)

// ---------------- scratch (bf16 hi/lo pairs + fp32 scores) ----------------
__device__ __nv_bfloat16 g_hTh[(size_t)BB*CL], g_hTl[(size_t)BB*CL];   // hT [B][L][C]
__device__ __nv_bfloat16 g_qh [(size_t)BB*CL], g_ql [(size_t)BB*CL];   // qT [B][L][C]
__device__ __nv_bfloat16 g_kh [(size_t)BB*CL], g_kl [(size_t)BB*CL];   // kT [B][L][C]
__device__ __nv_bfloat16 g_vh [(size_t)BB*CL], g_vl [(size_t)BB*CL];   // v  [B][C][L]
__device__ __nv_bfloat16 g_h2h[(size_t)BB*CL], g_h2l[(size_t)BB*CL];   // h2T[B][L][C]
__device__ float         g_s  [(size_t)BB*LLEN*LLEN];                  // scores fp32
__device__ __nv_bfloat16 g_sh [(size_t)BB*LLEN*LLEN], g_sl[(size_t)BB*LLEN*LLEN];
__device__ __nv_bfloat16 g_wh [4*CC*CC], g_wl[4*CC*CC];                // wq,wk,wv,wo
__device__ float g_stats[BB*NGRP*2];

// ---------------- helpers ----------------
__device__ __forceinline__ uint32_t smem_u32(const void* p){
    uint32_t a;
    asm("{ .reg .u64 t; cvta.to.shared.u64 t, %1; cvt.u32.u64 %0, t; }" : "=r"(a) : "l"(p));
    return a;
}
__device__ __forceinline__ void cp16(uint32_t s, const void* g){
    asm volatile("cp.async.cg.shared.global [%0], [%1], 16;" :: "r"(s), "l"(g));
}
#define CP_COMMIT() asm volatile("cp.async.commit_group;" ::: "memory")
#define CP_WAIT1()  asm volatile("cp.async.wait_group 1;" ::: "memory")

#define LDX4(r0,r1,r2,r3,addr) \
    asm volatile("ldmatrix.sync.aligned.m8n8.x4.shared.b16 {%0,%1,%2,%3}, [%4];" \
        : "=r"(r0), "=r"(r1), "=r"(r2), "=r"(r3) : "r"(addr))

#define MMA16816(d, a, b) \
    asm volatile("mma.sync.aligned.m16n8k16.row.col.f32.bf16.bf16.f32 " \
        "{%0,%1,%2,%3}, {%4,%5,%6,%7}, {%8,%9}, {%0,%1,%2,%3};" \
        : "+f"((d)[0]), "+f"((d)[1]), "+f"((d)[2]), "+f"((d)[3]) \
        : "r"((a)[0]), "r"((a)[1]), "r"((a)[2]), "r"((a)[3]), "r"((b)[0]), "r"((b)[1]))

// hi = truncate fp32->bf16 (exact residual), lo = rn(x - hi); pack 2 cols per u32
__device__ __forceinline__ void split2pack(float v0, float v1, uint32_t& hi, uint32_t& lo){
    uint32_t u0 = __float_as_uint(v0) & 0xffff0000u;
    uint32_t u1 = __float_as_uint(v1) & 0xffff0000u;
    hi = (u0 >> 16) | u1;
    float r0 = v0 - __uint_as_float(u0);
    float r1 = v1 - __uint_as_float(u1);
    asm("cvt.rn.bf16x2.f32 %0, %1, %2;" : "=r"(lo) : "f"(r1), "f"(r0));
}
__device__ __forceinline__ void split1(float v, __nv_bfloat16* hp, __nv_bfloat16* lp){
    uint32_t u = __float_as_uint(v) & 0xffff0000u;
    unsigned short hs = (unsigned short)(u >> 16);
    *(unsigned short*)hp = hs;
    *lp = __float2bfloat16(v - __uint_as_float(u));
}

// ---------------- HMMA GEMM ----------------
// D[M,N] = scale * sum_k A[m][k]*B[n][k] (+biasM)(+biasN)(+resid)
// A,B: bf16 hi/lo, K-contiguous rows (lda=ldb=K). Tile 128x128, BK=32, 3-stage cp.async.
#define ROWSTR 80            // bytes per smem row (32 bf16 data + pad)
#define BUF_B  (128*ROWSTR)  // 10240 per buffer
#define STG_B  (4*BUF_B)     // Ah,Al,Bh,Bl
#define NSTAGE 3
#define DYN_SMEM (NSTAGE*STG_B)

__global__ void __launch_bounds__(256)
hmma_gemm(const __nv_bfloat16* __restrict__ Ah, const __nv_bfloat16* __restrict__ Al,
          const __nv_bfloat16* __restrict__ Bh, const __nv_bfloat16* __restrict__ Bl,
          int K, int ldc, long sA, long sB, long sC,
          float* __restrict__ Cf, __nv_bfloat16* __restrict__ Ch, __nv_bfloat16* __restrict__ Cl,
          const float* __restrict__ biasM, const float* __restrict__ biasN,
          const float* __restrict__ resid, float scale)
{
    extern __shared__ char dsm[];
    const uint32_t smem0 = smem_u32(dsm);
    const int tid = threadIdx.x, lane = tid & 31, wid = tid >> 5;
    const int warpM = (wid & 3) * 32, warpN = (wid >> 2) * 64;
    const int bz = blockIdx.z;
    Ah += (size_t)bz * sA;  Al += (size_t)bz * sA;
    Bh += (size_t)bz * sB;  Bl += (size_t)bz * sB;
    if (Cf)    Cf    += (size_t)bz * sC;
    if (Ch)  { Ch    += (size_t)bz * sC; Cl += (size_t)bz * sC; }
    if (resid) resid += (size_t)bz * sC;
    const int m0 = blockIdx.y * 128, n0 = blockIdx.x * 128;
    const int niter = K >> 5;

    // cp.async mapping: 8 chunks/thread: buf = j>>1, idx2 = tid + (j&1)*256
    // row = idx2>>2 (0..127), seg = idx2&3 (16B each)
    const int c_row = tid >> 2, c_seg = tid & 3;

    auto issue = [&](int kt){
        const int kk = kt * 32;
        const uint32_t sb = smem0 + (kt % NSTAGE) * STG_B;
        #pragma unroll
        for (int j = 0; j < 8; j++){
            const int buf = j >> 1;
            const int row = c_row + ((j & 1) << 6);   // tid>>2 + 64*(j&1)
            const int seg = c_seg;
            const __nv_bfloat16* gp;
            if      (buf == 0) gp = Ah + (size_t)(m0 + row) * K + kk + seg * 8;
            else if (buf == 1) gp = Al + (size_t)(m0 + row) * K + kk + seg * 8;
            else if (buf == 2) gp = Bh + (size_t)(n0 + row) * K + kk + seg * 8;
            else               gp = Bl + (size_t)(n0 + row) * K + kk + seg * 8;
            cp16(sb + buf * BUF_B + row * ROWSTR + seg * 16, gp);
        }
        CP_COMMIT();
    };

    float acc[2][8][4];
    #pragma unroll
    for (int i = 0; i < 2; i++)
        #pragma unroll
        for (int j = 0; j < 8; j++)
            #pragma unroll
            for (int t = 0; t < 4; t++) acc[i][j][t] = 0.f;

    // ldmatrix lane addressing (bytes)
    const uint32_t aOff = (uint32_t)((warpM + (lane & 15)) * ROWSTR + ((lane >> 4) << 4));
    const uint32_t bRow = (uint32_t)(warpN + ((lane >> 4) << 3) + (lane & 7));
    const uint32_t bOff = (uint32_t)(bRow * ROWSTR + (((lane >> 3) & 1) << 4));

    issue(0); issue(1);

    for (int kt = 0; kt < niter; kt++){
        CP_WAIT1();
        __syncthreads();
        const uint32_t sb = smem0 + (kt % NSTAGE) * STG_B;
        #pragma unroll
        for (int k16 = 0; k16 < 2; k16++){
            const uint32_t ko = (uint32_t)(k16 * 32);
            uint32_t a_h[2][4], a_l[2][4], b_h[4][4], b_l[4][4];
            #pragma unroll
            for (int mt = 0; mt < 2; mt++){
                uint32_t ad = sb + aOff + mt * (16*ROWSTR) + ko;
                LDX4(a_h[mt][0], a_h[mt][1], a_h[mt][2], a_h[mt][3], ad);
                LDX4(a_l[mt][0], a_l[mt][1], a_l[mt][2], a_l[mt][3], ad + BUF_B);
            }
            #pragma unroll
            for (int p = 0; p < 4; p++){
                uint32_t bd = sb + 2*BUF_B + bOff + p * (16*ROWSTR) + ko;
                LDX4(b_h[p][0], b_h[p][1], b_h[p][2], b_h[p][3], bd);
                LDX4(b_l[p][0], b_l[p][1], b_l[p][2], b_l[p][3], bd + BUF_B);
            }
            #pragma unroll
            for (int mt = 0; mt < 2; mt++)
                #pragma unroll
                for (int nt = 0; nt < 8; nt++){
                    uint32_t* bh = &b_h[nt >> 1][(nt & 1) * 2];
                    uint32_t* bl = &b_l[nt >> 1][(nt & 1) * 2];
                    MMA16816(acc[mt][nt], a_h[mt], bh);
                    MMA16816(acc[mt][nt], a_h[mt], bl);
                    MMA16816(acc[mt][nt], a_l[mt], bh);
                }
        }
        if (kt + 2 < niter) issue(kt + 2);
        else CP_COMMIT();
    }

    // ---- epilogue: fragments -> gmem ----
    #pragma unroll
    for (int mt = 0; mt < 2; mt++){
        const int r0 = m0 + warpM + mt * 16 + (lane >> 2);
        const int r1 = r0 + 8;
        const float bm0 = biasM ? biasM[r0] : 0.f;
        const float bm1 = biasM ? biasM[r1] : 0.f;
        #pragma unroll
        for (int nt = 0; nt < 8; nt++){
            const int c = n0 + warpN + nt * 8 + ((lane & 3) << 1);
            float v0 = acc[mt][nt][0] * scale + bm0;
            float v1 = acc[mt][nt][1] * scale + bm0;
            float v2 = acc[mt][nt][2] * scale + bm1;
            float v3 = acc[mt][nt][3] * scale + bm1;
            if (biasN){
                float2 bn = *(const float2*)&biasN[c];
                v0 += bn.x; v1 += bn.y; v2 += bn.x; v3 += bn.y;
            }
            const size_t o0 = (size_t)r0 * ldc + c;
            const size_t o1 = (size_t)r1 * ldc + c;
            if (resid){
                float2 x0 = *(const float2*)&resid[o0];
                float2 x1 = *(const float2*)&resid[o1];
                v0 += x0.x; v1 += x0.y; v2 += x1.x; v3 += x1.y;
            }
            if (Cf){
                *(float2*)&Cf[o0] = make_float2(v0, v1);
                *(float2*)&Cf[o1] = make_float2(v2, v3);
            }
            if (Ch){
                uint32_t h01, l01, h23, l23;
                split2pack(v0, v1, h01, l01);
                split2pack(v2, v3, h23, l23);
                *(uint32_t*)&Ch[o0] = h01;  *(uint32_t*)&Cl[o0] = l01;
                *(uint32_t*)&Ch[o1] = h23;  *(uint32_t*)&Cl[o1] = l23;
            }
        }
    }
}

// ---------------- weight convert (4 weights -> bf16 hi/lo) ----------------
__global__ void __launch_bounds__(256) wconv(const float* __restrict__ w0, const float* __restrict__ w1,
                                             const float* __restrict__ w2, const float* __restrict__ w3,
                                             __nv_bfloat16* __restrict__ hi, __nv_bfloat16* __restrict__ lo)
{
    int i = blockIdx.x * 256 + threadIdx.x;   // per float4
    int w = i >> 16;                           // 65536 float4 per 512x512 weight
    int off = (i & 65535) * 4;
    const float* src = (w == 0) ? w0 : (w == 1) ? w1 : (w == 2) ? w2 : w3;
    float4 v = *(const float4*)(src + off);
    uint32_t h01, l01, h23, l23;
    split2pack(v.x, v.y, h01, l01);
    split2pack(v.z, v.w, h23, l23);
    size_t o = (size_t)w * CC * CC + off;
    *(uint32_t*)&hi[o]   = h01;  *(uint32_t*)&lo[o]   = l01;
    *(uint32_t*)&hi[o+2] = h23;  *(uint32_t*)&lo[o+2] = l23;
}

// ---------------- GroupNorm stats ----------------
__global__ void __launch_bounds__(1024) gn_stats(const float* __restrict__ x, float* __restrict__ stats)
{
    int b = blockIdx.x >> 3, g = blockIdx.x & 7;
    const float* xp = x + ((size_t)b*CC + (size_t)g*CPG) * LLEN;
    const int n = CPG * LLEN;
    int tid = threadIdx.x;
    float s = 0.f, ss = 0.f;
    for (int i = tid; i < n; i += 1024){ float v = xp[i]; s += v; ss += v*v; }
    __shared__ float rs[32], rss[32];
    #pragma unroll
    for (int o = 16; o; o >>= 1){
        s  += __shfl_xor_sync(0xffffffffu, s,  o);
        ss += __shfl_xor_sync(0xffffffffu, ss, o);
    }
    if ((tid & 31) == 0){ rs[tid>>5] = s; rss[tid>>5] = ss; }
    __syncthreads();
    if (tid == 0){
        float t = 0.f, t2 = 0.f;
        #pragma unroll
        for (int i = 0; i < 32; i++){ t += rs[i]; t2 += rss[i]; }
        float mean = t / (float)n;
        float var  = t2 / (float)n - mean*mean;
        stats[blockIdx.x*2]   = mean;
        stats[blockIdx.x*2+1] = rsqrtf(var + 1e-6f);
    }
}

// ---------------- GroupNorm apply + transpose -> hT bf16 pair ----------------
__global__ void __launch_bounds__(256) gn_apply_t(const float* __restrict__ x,
                                                  const float* __restrict__ stats,
                                                  const float* __restrict__ gamma,
                                                  const float* __restrict__ beta,
                                                  __nv_bfloat16* __restrict__ hTh,
                                                  __nv_bfloat16* __restrict__ hTl)
{
    __shared__ float tile[64][33];
    int b = blockIdx.z, g = blockIdx.y, l0 = blockIdx.x * 32;
    float mean = stats[(b*NGRP+g)*2], inv = stats[(b*NGRP+g)*2+1];
    const float* xp = x + ((size_t)b*CC + (size_t)g*CPG) * LLEN;
    int tid = threadIdx.x;
    #pragma unroll
    for (int i = 0; i < 8; i++){
        int idx = tid + i*256; int c = idx >> 5, l = idx & 31;
        float v = xp[(size_t)c*LLEN + l0 + l];
        tile[c][l] = (v - mean) * inv * gamma[g*CPG + c] + beta[g*CPG + c];
    }
    __syncthreads();
    size_t base = (size_t)b * LLEN * CC;
    #pragma unroll
    for (int i = 0; i < 8; i++){
        int idx = tid + i*256; int l = idx >> 6, c = idx & 63;
        size_t o = base + (size_t)(l0 + l)*CC + g*CPG + c;
        split1(tile[c][l], &hTh[o], &hTl[o]);
    }
}

// ---------------- row softmax fp32 -> bf16 pair ----------------
__global__ void __launch_bounds__(256) softmax_kernel(const float* __restrict__ S,
                                                      __nv_bfloat16* __restrict__ Sh,
                                                      __nv_bfloat16* __restrict__ Sl)
{
    const float* row = S + (size_t)blockIdx.x * LLEN;
    size_t ob = (size_t)blockIdx.x * LLEN;
    int tid = threadIdx.x;
    float v[8];
    float mx = -1e30f;
    #pragma unroll
    for (int i = 0; i < 8; i++){ v[i] = row[tid + 256*i]; mx = fmaxf(mx, v[i]); }
    __shared__ float rmax[8], rsum[8];
    #pragma unroll
    for (int o = 16; o; o >>= 1) mx = fmaxf(mx, __shfl_xor_sync(0xffffffffu, mx, o));
    if ((tid & 31) == 0) rmax[tid >> 5] = mx;
    __syncthreads();
    float m = rmax[0];
    #pragma unroll
    for (int i = 1; i < 8; i++) m = fmaxf(m, rmax[i]);
    float sm = 0.f;
    #pragma unroll
    for (int i = 0; i < 8; i++){ v[i] = __expf(v[i] - m); sm += v[i]; }
    #pragma unroll
    for (int o = 16; o; o >>= 1) sm += __shfl_xor_sync(0xffffffffu, sm, o);
    if ((tid & 31) == 0) rsum[tid >> 5] = sm;
    __syncthreads();
    float tot = 0.f;
    #pragma unroll
    for (int i = 0; i < 8; i++) tot += rsum[i];
    float inv = 1.f / tot;
    #pragma unroll
    for (int i = 0; i < 8; i++)
        split1(v[i] * inv, &Sh[ob + tid + 256*i], &Sl[ob + tid + 256*i]);
}

// ---------------- launch ----------------
extern "C" void kernel_launch(void* const* d_in, const int* in_sizes, int n_in,
                              void* d_out, int out_size)
{
    const float* x     = (const float*)d_in[0];
    const float* gamma = (const float*)d_in[1];
    const float* beta  = (const float*)d_in[2];
    const float* wq    = (const float*)d_in[3];
    const float* bq    = (const float*)d_in[4];
    const float* wk    = (const float*)d_in[5];
    const float* bk    = (const float*)d_in[6];
    const float* wv    = (const float*)d_in[7];
    const float* bv    = (const float*)d_in[8];
    const float* wo    = (const float*)d_in[9];
    const float* bo    = (const float*)d_in[10];
    float* out = (float*)d_out;

    __nv_bfloat16 *hTh,*hTl,*qh,*ql,*kh,*kl,*vh,*vl,*h2h,*h2l,*sh,*sl,*wh,*wl;
    float *s, *stats;
    cudaGetSymbolAddress((void**)&hTh, g_hTh); cudaGetSymbolAddress((void**)&hTl, g_hTl);
    cudaGetSymbolAddress((void**)&qh,  g_qh);  cudaGetSymbolAddress((void**)&ql,  g_ql);
    cudaGetSymbolAddress((void**)&kh,  g_kh);  cudaGetSymbolAddress((void**)&kl,  g_kl);
    cudaGetSymbolAddress((void**)&vh,  g_vh);  cudaGetSymbolAddress((void**)&vl,  g_vl);
    cudaGetSymbolAddress((void**)&h2h, g_h2h); cudaGetSymbolAddress((void**)&h2l, g_h2l);
    cudaGetSymbolAddress((void**)&sh,  g_sh);  cudaGetSymbolAddress((void**)&sl,  g_sl);
    cudaGetSymbolAddress((void**)&wh,  g_wh);  cudaGetSymbolAddress((void**)&wl,  g_wl);
    cudaGetSymbolAddress((void**)&s,   g_s);   cudaGetSymbolAddress((void**)&stats, g_stats);

    cudaFuncSetAttribute(hmma_gemm, cudaFuncAttributeMaxDynamicSharedMemorySize, DYN_SMEM);

    const long LL = (long)LLEN * LLEN;
    const float scl = 1.0f / sqrtf((float)CC);

    gn_stats<<<BB*NGRP, 1024>>>(x, stats);
    wconv<<<1024, 256>>>(wq, wk, wv, wo, wh, wl);
    gn_apply_t<<<dim3(LLEN/32, NGRP, BB), 256>>>(x, stats, gamma, beta, hTh, hTl);

    dim3 blk(256);
    // qT[l,c] = sum hT[l,:]*wq[c,:] + bq[c]     M=L,N=C,K=C
    hmma_gemm<<<dim3(4,16,BB), blk, DYN_SMEM>>>(hTh, hTl, wh + 0*CC*CC, wl + 0*CC*CC,
        CC, CC, (long)CL, 0L, (long)CL, nullptr, qh, ql, nullptr, bq, nullptr, 1.f);
    hmma_gemm<<<dim3(4,16,BB), blk, DYN_SMEM>>>(hTh, hTl, wh + 1*CC*CC, wl + 1*CC*CC,
        CC, CC, (long)CL, 0L, (long)CL, nullptr, kh, kl, nullptr, bk, nullptr, 1.f);
    // v[c,l] = sum wv[c,:]*hT[l,:] + bv[c]      M=C,N=L,K=C
    hmma_gemm<<<dim3(16,4,BB), blk, DYN_SMEM>>>(wh + 2*CC*CC, wl + 2*CC*CC, hTh, hTl,
        CC, LLEN, 0L, (long)CL, (long)CL, nullptr, vh, vl, bv, nullptr, nullptr, 1.f);
    // S[i,j] = scl * sum qT[i,:]*kT[j,:]        M=L,N=L,K=C
    hmma_gemm<<<dim3(16,16,BB), blk, DYN_SMEM>>>(qh, ql, kh, kl,
        CC, LLEN, (long)CL, (long)CL, LL, s, nullptr, nullptr, nullptr, nullptr, nullptr, scl);

    softmax_kernel<<<BB*LLEN, 256>>>(s, sh, sl);

    // h2T[i,c] = sum S[i,:]*v[c,:]              M=L,N=C,K=L
    hmma_gemm<<<dim3(4,16,BB), blk, DYN_SMEM>>>(sh, sl, vh, vl,
        LLEN, CC, LL, (long)CL, (long)CL, nullptr, h2h, h2l, nullptr, nullptr, nullptr, 1.f);
    // out[c,l] = x + sum wo[c,:]*h2T[l,:] + bo  M=C,N=L,K=C
    hmma_gemm<<<dim3(16,4,BB), blk, DYN_SMEM>>>(wh + 3*CC*CC, wl + 3*CC*CC, h2h, h2l,
        CC, LLEN, 0L, (long)CL, (long)CL, out, nullptr, nullptr, bo, nullptr, x, 1.f);
}

// round 4
// speedup vs baseline: 2.7361x; 1.1092x over previous
#include <cuda_runtime.h>
#include <cuda_bf16.h>
#include <cstdint>
#include <math.h>

#define BB 8
#define CC 512
#define LLEN 2048
#define NGRP 8
#define CPG 64
#define CL (CC*LLEN)

// ---------------- scratch ----------------
__device__ __nv_bfloat16 g_hTh[(size_t)BB*CL], g_hTl[(size_t)BB*CL];   // hT [B][L][C]
__device__ __nv_bfloat16 g_qh [(size_t)BB*CL], g_ql [(size_t)BB*CL];   // qT [B][L][C]
__device__ __nv_bfloat16 g_kh [(size_t)BB*CL], g_kl [(size_t)BB*CL];   // kT [B][L][C]
__device__ __nv_bfloat16 g_vh [(size_t)BB*CL], g_vl [(size_t)BB*CL];   // v  [B][C][L]
__device__ __nv_bfloat16 g_h2h[(size_t)BB*CL], g_h2l[(size_t)BB*CL];   // h2T[B][L][C]
__device__ __nv_bfloat16 g_sh [(size_t)BB*LLEN*LLEN], g_sl[(size_t)BB*LLEN*LLEN];
__device__ __nv_bfloat16 g_wh [4*CC*CC], g_wl[4*CC*CC];                // wq,wk,wv,wo
__device__ float g_stats[BB*NGRP*2];

// ---------------- helpers ----------------
__device__ __forceinline__ uint32_t smem_u32(const void* p){
    uint32_t a;
    asm("{ .reg .u64 t; cvta.to.shared.u64 t, %1; cvt.u32.u64 %0, t; }" : "=r"(a) : "l"(p));
    return a;
}
__device__ __forceinline__ void cp16(uint32_t s, const void* g){
    asm volatile("cp.async.cg.shared.global [%0], [%1], 16;" :: "r"(s), "l"(g));
}
#define CP_COMMIT() asm volatile("cp.async.commit_group;" ::: "memory")
#define CP_WAIT1()  asm volatile("cp.async.wait_group 1;" ::: "memory")
#define CP_WAIT0()  asm volatile("cp.async.wait_group 0;" ::: "memory")

#define LDX4(r0,r1,r2,r3,addr) \
    asm volatile("ldmatrix.sync.aligned.m8n8.x4.shared.b16 {%0,%1,%2,%3}, [%4];" \
        : "=r"(r0), "=r"(r1), "=r"(r2), "=r"(r3) : "r"(addr))

#define MMA16816(d, a, b) \
    asm volatile("mma.sync.aligned.m16n8k16.row.col.f32.bf16.bf16.f32 " \
        "{%0,%1,%2,%3}, {%4,%5,%6,%7}, {%8,%9}, {%0,%1,%2,%3};" \
        : "+f"((d)[0]), "+f"((d)[1]), "+f"((d)[2]), "+f"((d)[3]) \
        : "r"((a)[0]), "r"((a)[1]), "r"((a)[2]), "r"((a)[3]), "r"((b)[0]), "r"((b)[1]))

// hi = truncate fp32->bf16 (exact residual), lo = rn(x - hi)
__device__ __forceinline__ void split2pack(float v0, float v1, uint32_t& hi, uint32_t& lo){
    uint32_t u0 = __float_as_uint(v0) & 0xffff0000u;
    uint32_t u1 = __float_as_uint(v1) & 0xffff0000u;
    hi = (u0 >> 16) | u1;
    float r0 = v0 - __uint_as_float(u0);
    float r1 = v1 - __uint_as_float(u1);
    asm("cvt.rn.bf16x2.f32 %0, %1, %2;" : "=r"(lo) : "f"(r1), "f"(r0));
}
__device__ __forceinline__ void split1(float v, __nv_bfloat16* hp, __nv_bfloat16* lp){
    uint32_t u = __float_as_uint(v) & 0xffff0000u;
    *(unsigned short*)hp = (unsigned short)(u >> 16);
    *lp = __float2bfloat16(v - __uint_as_float(u));
}

// ---------------- HMMA GEMM (BK=64, swizzled 128B rows, 3-stage) ----------------
#define BUF_B  16384          // 128 rows x 128 bytes
#define STG_B  (4*BUF_B)      // Ah,Al,Bh,Bl
#define NSTAGE 3
#define DYN_SMEM (NSTAGE*STG_B + 128)

__global__ void __launch_bounds__(256)
hmma_gemm(const __nv_bfloat16* __restrict__ Ah, const __nv_bfloat16* __restrict__ Al,
          const __nv_bfloat16* __restrict__ Bh, const __nv_bfloat16* __restrict__ Bl,
          int K, int ldc, long sA, long sB, long sC,
          float* __restrict__ Cf, __nv_bfloat16* __restrict__ Ch, __nv_bfloat16* __restrict__ Cl,
          const float* __restrict__ biasM, const float* __restrict__ biasN,
          const float* __restrict__ resid, float scale)
{
    extern __shared__ char dsm[];
    const uint32_t sbase = (smem_u32(dsm) + 127u) & ~127u;
    const int tid = threadIdx.x, lane = tid & 31, wid = tid >> 5;
    const int warpM = (wid & 3) * 32, warpN = (wid >> 2) * 64;
    const int bz = blockIdx.z;
    Ah += (size_t)bz * sA;  Al += (size_t)bz * sA;
    Bh += (size_t)bz * sB;  Bl += (size_t)bz * sB;
    if (Cf)    Cf    += (size_t)bz * sC;
    if (Ch)  { Ch    += (size_t)bz * sC; Cl += (size_t)bz * sC; }
    if (resid) resid += (size_t)bz * sC;
    const int m0 = blockIdx.y * 128, n0 = blockIdx.x * 128;
    const int niter = K >> 6;

    // cp.async mapping: 16 chunks/thread; buf=j>>2, idx=tid+(j&3)*256, row=idx>>3, seg=idx&7
    const int c_row = tid >> 3;                 // +128*(j&3 part folded below)
    const int c_seg = tid & 7;

    auto issue = [&](int kt){
        const int kk = kt * 64;
        const uint32_t sb = sbase + (kt % NSTAGE) * STG_B;
        #pragma unroll
        for (int j = 0; j < 16; j++){
            const int buf = j >> 2;
            const int row = c_row + ((j & 3) << 5);     // idx>>3, idx = tid + (j&3)*256
            const int seg = c_seg;
            const __nv_bfloat16* gp;
            if      (buf == 0) gp = Ah + (size_t)(m0 + row) * K + kk + seg * 8;
            else if (buf == 1) gp = Al + (size_t)(m0 + row) * K + kk + seg * 8;
            else if (buf == 2) gp = Bh + (size_t)(n0 + row) * K + kk + seg * 8;
            else               gp = Bl + (size_t)(n0 + row) * K + kk + seg * 8;
            const uint32_t c = (uint32_t)((seg * 16) ^ ((row & 7) << 4));
            cp16(sb + buf * BUF_B + row * 128 + c, gp);
        }
        CP_COMMIT();
    };

    float acc[2][8][4];
    #pragma unroll
    for (int i = 0; i < 2; i++)
        #pragma unroll
        for (int j = 0; j < 8; j++)
            #pragma unroll
            for (int t = 0; t < 4; t++) acc[i][j][t] = 0.f;

    // ldmatrix lane addressing
    const int aRow = warpM + (lane & 15);
    const uint32_t aSz = (uint32_t)((aRow & 7) << 4);
    const uint32_t aC  = (uint32_t)((lane >> 4) << 4);       // 0 or 16
    const uint32_t aB0 = (uint32_t)(aRow * 128);
    const int bRow = warpN + ((lane >> 4) << 3) + (lane & 7);
    const uint32_t bSz = (uint32_t)((bRow & 7) << 4);
    const uint32_t bC  = (uint32_t)(((lane >> 3) & 1) << 4); // 0 or 16
    const uint32_t bB0 = (uint32_t)(bRow * 128);

    issue(0); if (niter > 1) issue(1);

    for (int kt = 0; kt < niter; kt++){
        if (kt + 1 < niter) CP_WAIT1(); else CP_WAIT0();
        __syncthreads();
        if (kt + 2 < niter) issue(kt + 2);       // overlap loads with this stage's compute
        const uint32_t sb = sbase + (kt % NSTAGE) * STG_B;
        #pragma unroll
        for (int ko = 0; ko < 4; ko++){
            const uint32_t kb = (uint32_t)(ko * 32);
            uint32_t a_h[2][4], a_l[2][4], b_h[4][4], b_l[4][4];
            #pragma unroll
            for (int mt = 0; mt < 2; mt++){
                uint32_t ad = sb + aB0 + (uint32_t)(mt * 16 * 128) + ((aC + kb) ^ aSz);
                LDX4(a_h[mt][0], a_h[mt][1], a_h[mt][2], a_h[mt][3], ad);
                LDX4(a_l[mt][0], a_l[mt][1], a_l[mt][2], a_l[mt][3], ad + BUF_B);
            }
            #pragma unroll
            for (int p = 0; p < 4; p++){
                uint32_t bd = sb + 2*BUF_B + bB0 + (uint32_t)(p * 16 * 128) + ((bC + kb) ^ bSz);
                LDX4(b_h[p][0], b_h[p][1], b_h[p][2], b_h[p][3], bd);
                LDX4(b_l[p][0], b_l[p][1], b_l[p][2], b_l[p][3], bd + BUF_B);
            }
            #pragma unroll
            for (int mt = 0; mt < 2; mt++)
                #pragma unroll
                for (int nt = 0; nt < 8; nt++){
                    uint32_t* bh = &b_h[nt >> 1][(nt & 1) * 2];
                    uint32_t* bl = &b_l[nt >> 1][(nt & 1) * 2];
                    MMA16816(acc[mt][nt], a_h[mt], bh);
                    MMA16816(acc[mt][nt], a_h[mt], bl);
                    MMA16816(acc[mt][nt], a_l[mt], bh);
                }
        }
        __syncthreads();
    }

    // ---- epilogue ----
    #pragma unroll
    for (int mt = 0; mt < 2; mt++){
        const int r0 = m0 + warpM + mt * 16 + (lane >> 2);
        const int r1 = r0 + 8;
        const float bm0 = biasM ? biasM[r0] : 0.f;
        const float bm1 = biasM ? biasM[r1] : 0.f;
        #pragma unroll
        for (int nt = 0; nt < 8; nt++){
            const int c = n0 + warpN + nt * 8 + ((lane & 3) << 1);
            float v0 = acc[mt][nt][0] * scale + bm0;
            float v1 = acc[mt][nt][1] * scale + bm0;
            float v2 = acc[mt][nt][2] * scale + bm1;
            float v3 = acc[mt][nt][3] * scale + bm1;
            if (biasN){
                float2 bn = *(const float2*)&biasN[c];
                v0 += bn.x; v1 += bn.y; v2 += bn.x; v3 += bn.y;
            }
            const size_t o0 = (size_t)r0 * ldc + c;
            const size_t o1 = (size_t)r1 * ldc + c;
            if (resid){
                float2 x0 = *(const float2*)&resid[o0];
                float2 x1 = *(const float2*)&resid[o1];
                v0 += x0.x; v1 += x0.y; v2 += x1.x; v3 += x1.y;
            }
            if (Cf){
                *(float2*)&Cf[o0] = make_float2(v0, v1);
                *(float2*)&Cf[o1] = make_float2(v2, v3);
            }
            if (Ch){
                uint32_t h01, l01, h23, l23;
                split2pack(v0, v1, h01, l01);
                split2pack(v2, v3, h23, l23);
                *(uint32_t*)&Ch[o0] = h01;  *(uint32_t*)&Cl[o0] = l01;
                *(uint32_t*)&Ch[o1] = h23;  *(uint32_t*)&Cl[o1] = l23;
            }
        }
    }
}

// ---------------- weight convert ----------------
__global__ void __launch_bounds__(256) wconv(const float* __restrict__ w0, const float* __restrict__ w1,
                                             const float* __restrict__ w2, const float* __restrict__ w3,
                                             __nv_bfloat16* __restrict__ hi, __nv_bfloat16* __restrict__ lo)
{
    int i = blockIdx.x * 256 + threadIdx.x;
    int w = i >> 16;
    int off = (i & 65535) * 4;
    const float* src = (w == 0) ? w0 : (w == 1) ? w1 : (w == 2) ? w2 : w3;
    float4 v = *(const float4*)(src + off);
    uint32_t h01, l01, h23, l23;
    split2pack(v.x, v.y, h01, l01);
    split2pack(v.z, v.w, h23, l23);
    size_t o = (size_t)w * CC * CC + off;
    *(uint32_t*)&hi[o]   = h01;  *(uint32_t*)&lo[o]   = l01;
    *(uint32_t*)&hi[o+2] = h23;  *(uint32_t*)&lo[o+2] = l23;
}

// ---------------- GroupNorm stats ----------------
__global__ void __launch_bounds__(1024) gn_stats(const float* __restrict__ x, float* __restrict__ stats)
{
    int b = blockIdx.x >> 3, g = blockIdx.x & 7;
    const float* xp = x + ((size_t)b*CC + (size_t)g*CPG) * LLEN;
    const int n = CPG * LLEN;
    int tid = threadIdx.x;
    float s = 0.f, ss = 0.f;
    for (int i = tid; i < n; i += 1024){ float v = xp[i]; s += v; ss += v*v; }
    __shared__ float rs[32], rss[32];
    #pragma unroll
    for (int o = 16; o; o >>= 1){
        s  += __shfl_xor_sync(0xffffffffu, s,  o);
        ss += __shfl_xor_sync(0xffffffffu, ss, o);
    }
    if ((tid & 31) == 0){ rs[tid>>5] = s; rss[tid>>5] = ss; }
    __syncthreads();
    if (tid == 0){
        float t = 0.f, t2 = 0.f;
        #pragma unroll
        for (int i = 0; i < 32; i++){ t += rs[i]; t2 += rss[i]; }
        float mean = t / (float)n;
        float var  = t2 / (float)n - mean*mean;
        stats[blockIdx.x*2]   = mean;
        stats[blockIdx.x*2+1] = rsqrtf(var + 1e-6f);
    }
}

// ---------------- GroupNorm apply + transpose -> hT hi/lo ----------------
__global__ void __launch_bounds__(256) gn_apply_t(const float* __restrict__ x,
                                                  const float* __restrict__ stats,
                                                  const float* __restrict__ gamma,
                                                  const float* __restrict__ beta,
                                                  __nv_bfloat16* __restrict__ hTh,
                                                  __nv_bfloat16* __restrict__ hTl)
{
    __shared__ float tile[64][33];
    int b = blockIdx.z, g = blockIdx.y, l0 = blockIdx.x * 32;
    float mean = stats[(b*NGRP+g)*2], inv = stats[(b*NGRP+g)*2+1];
    const float* xp = x + ((size_t)b*CC + (size_t)g*CPG) * LLEN;
    int tid = threadIdx.x;
    #pragma unroll
    for (int i = 0; i < 8; i++){
        int idx = tid + i*256; int c = idx >> 5, l = idx & 31;
        float v = xp[(size_t)c*LLEN + l0 + l];
        tile[c][l] = (v - mean) * inv * gamma[g*CPG + c] + beta[g*CPG + c];
    }
    __syncthreads();
    size_t base = (size_t)b * LLEN * CC;
    #pragma unroll
    for (int i = 0; i < 8; i++){
        int idx = tid + i*256; int l = idx >> 6, c = idx & 63;
        size_t o = base + (size_t)(l0 + l)*CC + g*CPG + c;
        split1(tile[c][l], &hTh[o], &hTl[o]);
    }
}

// ---------------- row softmax over bf16 hi/lo pair, in place ----------------
__global__ void __launch_bounds__(256) softmax_kernel(__nv_bfloat16* __restrict__ Sh,
                                                      __nv_bfloat16* __restrict__ Sl)
{
    size_t ob = (size_t)blockIdx.x * LLEN;
    int tid = threadIdx.x;
    float v[8];
    float mx = -1e30f;
    #pragma unroll
    for (int i = 0; i < 8; i++){
        int idx = tid + 256*i;
        v[i] = __bfloat162float(Sh[ob + idx]) + __bfloat162float(Sl[ob + idx]);
        mx = fmaxf(mx, v[i]);
    }
    __shared__ float rmax[8], rsum[8];
    #pragma unroll
    for (int o = 16; o; o >>= 1) mx = fmaxf(mx, __shfl_xor_sync(0xffffffffu, mx, o));
    if ((tid & 31) == 0) rmax[tid >> 5] = mx;
    __syncthreads();
    float m = rmax[0];
    #pragma unroll
    for (int i = 1; i < 8; i++) m = fmaxf(m, rmax[i]);
    float sm = 0.f;
    #pragma unroll
    for (int i = 0; i < 8; i++){ v[i] = __expf(v[i] - m); sm += v[i]; }
    #pragma unroll
    for (int o = 16; o; o >>= 1) sm += __shfl_xor_sync(0xffffffffu, sm, o);
    if ((tid & 31) == 0) rsum[tid >> 5] = sm;
    __syncthreads();
    float tot = 0.f;
    #pragma unroll
    for (int i = 0; i < 8; i++) tot += rsum[i];
    float inv = 1.f / tot;
    #pragma unroll
    for (int i = 0; i < 8; i++){
        int idx = tid + 256*i;
        split1(v[i] * inv, &Sh[ob + idx], &Sl[ob + idx]);
    }
}

// ---------------- launch ----------------
extern "C" void kernel_launch(void* const* d_in, const int* in_sizes, int n_in,
                              void* d_out, int out_size)
{
    const float* x     = (const float*)d_in[0];
    const float* gamma = (const float*)d_in[1];
    const float* beta  = (const float*)d_in[2];
    const float* wq    = (const float*)d_in[3];
    const float* bq    = (const float*)d_in[4];
    const float* wk    = (const float*)d_in[5];
    const float* bk    = (const float*)d_in[6];
    const float* wv    = (const float*)d_in[7];
    const float* bv    = (const float*)d_in[8];
    const float* wo    = (const float*)d_in[9];
    const float* bo    = (const float*)d_in[10];
    float* out = (float*)d_out;

    __nv_bfloat16 *hTh,*hTl,*qh,*ql,*kh,*kl,*vh,*vl,*h2h,*h2l,*sh,*sl,*wh,*wl;
    float *stats;
    cudaGetSymbolAddress((void**)&hTh, g_hTh); cudaGetSymbolAddress((void**)&hTl, g_hTl);
    cudaGetSymbolAddress((void**)&qh,  g_qh);  cudaGetSymbolAddress((void**)&ql,  g_ql);
    cudaGetSymbolAddress((void**)&kh,  g_kh);  cudaGetSymbolAddress((void**)&kl,  g_kl);
    cudaGetSymbolAddress((void**)&vh,  g_vh);  cudaGetSymbolAddress((void**)&vl,  g_vl);
    cudaGetSymbolAddress((void**)&h2h, g_h2h); cudaGetSymbolAddress((void**)&h2l, g_h2l);
    cudaGetSymbolAddress((void**)&sh,  g_sh);  cudaGetSymbolAddress((void**)&sl,  g_sl);
    cudaGetSymbolAddress((void**)&wh,  g_wh);  cudaGetSymbolAddress((void**)&wl,  g_wl);
    cudaGetSymbolAddress((void**)&stats, g_stats);

    cudaFuncSetAttribute(hmma_gemm, cudaFuncAttributeMaxDynamicSharedMemorySize, DYN_SMEM);

    const long LL = (long)LLEN * LLEN;
    const float scl = 1.0f / sqrtf((float)CC);

    gn_stats<<<BB*NGRP, 1024>>>(x, stats);
    wconv<<<1024, 256>>>(wq, wk, wv, wo, wh, wl);
    gn_apply_t<<<dim3(LLEN/32, NGRP, BB), 256>>>(x, stats, gamma, beta, hTh, hTl);

    dim3 blk(256);
    // qT[l,c] = sum hT[l,:]*wq[c,:] + bq[c]     M=L,N=C,K=C
    hmma_gemm<<<dim3(4,16,BB), blk, DYN_SMEM>>>(hTh, hTl, wh + 0*CC*CC, wl + 0*CC*CC,
        CC, CC, (long)CL, 0L, (long)CL, nullptr, qh, ql, nullptr, bq, nullptr, 1.f);
    hmma_gemm<<<dim3(4,16,BB), blk, DYN_SMEM>>>(hTh, hTl, wh + 1*CC*CC, wl + 1*CC*CC,
        CC, CC, (long)CL, 0L, (long)CL, nullptr, kh, kl, nullptr, bk, nullptr, 1.f);
    // v[c,l] = sum wv[c,:]*hT[l,:] + bv[c]      M=C,N=L,K=C
    hmma_gemm<<<dim3(16,4,BB), blk, DYN_SMEM>>>(wh + 2*CC*CC, wl + 2*CC*CC, hTh, hTl,
        CC, LLEN, 0L, (long)CL, (long)CL, nullptr, vh, vl, bv, nullptr, nullptr, 1.f);
    // S[i,j] = scl * sum qT[i,:]*kT[j,:]        M=L,N=L,K=C  -> bf16 hi/lo direct
    hmma_gemm<<<dim3(16,16,BB), blk, DYN_SMEM>>>(qh, ql, kh, kl,
        CC, LLEN, (long)CL, (long)CL, LL, nullptr, sh, sl, nullptr, nullptr, nullptr, scl);

    softmax_kernel<<<BB*LLEN, 256>>>(sh, sl);

    // h2T[i,c] = sum S[i,:]*v[c,:]              M=L,N=C,K=L
    hmma_gemm<<<dim3(4,16,BB), blk, DYN_SMEM>>>(sh, sl, vh, vl,
        LLEN, CC, LL, (long)CL, (long)CL, nullptr, h2h, h2l, nullptr, nullptr, nullptr, 1.f);
    // out[c,l] = x + sum wo[c,:]*h2T[l,:] + bo  M=C,N=L,K=C
    hmma_gemm<<<dim3(16,4,BB), blk, DYN_SMEM>>>(wh + 3*CC*CC, wl + 3*CC*CC, h2h, h2l,
        CC, LLEN, 0L, (long)CL, (long)CL, out, nullptr, nullptr, bo, nullptr, x, 1.f);
}

// round 5
// speedup vs baseline: 2.7899x; 1.0197x over previous
#include <cuda_runtime.h>
#include <cuda_bf16.h>
#include <cstdint>
#include <math.h>

#define BB 8
#define CC 512
#define LLEN 2048
#define NGRP 8
#define CPG 64
#define CL (CC*LLEN)

// ---------------- scratch ----------------
__device__ __nv_bfloat16 g_hTh[(size_t)BB*CL], g_hTl[(size_t)BB*CL];   // hT [B][L][C]
__device__ __nv_bfloat16 g_qh [(size_t)BB*CL], g_ql [(size_t)BB*CL];   // qT [B][L][C]
__device__ __nv_bfloat16 g_kh [(size_t)BB*CL], g_kl [(size_t)BB*CL];   // kT [B][L][C]
__device__ __nv_bfloat16 g_vh [(size_t)BB*CL], g_vl [(size_t)BB*CL];   // v  [B][C][L]
__device__ __nv_bfloat16 g_h2h[(size_t)BB*CL], g_h2l[(size_t)BB*CL];   // h2T[B][L][C]
__device__ __nv_bfloat16 g_sh [(size_t)BB*LLEN*LLEN], g_sl[(size_t)BB*LLEN*LLEN];
__device__ __nv_bfloat16 g_wh [4*CC*CC], g_wl[4*CC*CC];                // wq,wk,wv,wo
__device__ float g_stats[BB*NGRP*2];

// ---------------- helpers ----------------
__device__ __forceinline__ uint32_t smem_u32(const void* p){
    uint32_t a;
    asm("{ .reg .u64 t; cvta.to.shared.u64 t, %1; cvt.u32.u64 %0, t; }" : "=r"(a) : "l"(p));
    return a;
}
__device__ __forceinline__ void cp16(uint32_t s, const void* g){
    asm volatile("cp.async.cg.shared.global [%0], [%1], 16;" :: "r"(s), "l"(g));
}
#define CP_COMMIT() asm volatile("cp.async.commit_group;" ::: "memory")
#define CP_WAIT1()  asm volatile("cp.async.wait_group 1;" ::: "memory")
#define CP_WAIT0()  asm volatile("cp.async.wait_group 0;" ::: "memory")

#define LDX4(r0,r1,r2,r3,addr) \
    asm volatile("ldmatrix.sync.aligned.m8n8.x4.shared.b16 {%0,%1,%2,%3}, [%4];" \
        : "=r"(r0), "=r"(r1), "=r"(r2), "=r"(r3) : "r"(addr))

#define MMA16816(d, a, b) \
    asm volatile("mma.sync.aligned.m16n8k16.row.col.f32.bf16.bf16.f32 " \
        "{%0,%1,%2,%3}, {%4,%5,%6,%7}, {%8,%9}, {%0,%1,%2,%3};" \
        : "+f"((d)[0]), "+f"((d)[1]), "+f"((d)[2]), "+f"((d)[3]) \
        : "r"((a)[0]), "r"((a)[1]), "r"((a)[2]), "r"((a)[3]), "r"((b)[0]), "r"((b)[1]))

// hi = truncate fp32->bf16 (exact residual), lo = rn(x - hi)
__device__ __forceinline__ void split2pack(float v0, float v1, uint32_t& hi, uint32_t& lo){
    uint32_t u0 = __float_as_uint(v0) & 0xffff0000u;
    uint32_t u1 = __float_as_uint(v1) & 0xffff0000u;
    hi = (u0 >> 16) | u1;
    float r0 = v0 - __uint_as_float(u0);
    float r1 = v1 - __uint_as_float(u1);
    asm("cvt.rn.bf16x2.f32 %0, %1, %2;" : "=r"(lo) : "f"(r1), "f"(r0));
}
__device__ __forceinline__ void split1(float v, __nv_bfloat16* hp, __nv_bfloat16* lp){
    uint32_t u = __float_as_uint(v) & 0xffff0000u;
    *(unsigned short*)hp = (unsigned short)(u >> 16);
    *lp = __float2bfloat16(v - __uint_as_float(u));
}

// ---------------- HMMA GEMM (BK=64, swizzled 128B rows, 3-stage, reg-pipelined) ----------------
#define BUF_B  16384          // 128 rows x 128 bytes
#define STG_B  (4*BUF_B)      // Ah,Al,Bh,Bl
#define NSTAGE 3
#define DYN_SMEM (NSTAGE*STG_B + 128)

__global__ void __launch_bounds__(256, 1)
hmma_gemm(const __nv_bfloat16* __restrict__ Ah, const __nv_bfloat16* __restrict__ Al,
          const __nv_bfloat16* __restrict__ Bh, const __nv_bfloat16* __restrict__ Bl,
          int K, int ldc, long sA, long sB, long sC,
          float* __restrict__ Cf, __nv_bfloat16* __restrict__ Ch, __nv_bfloat16* __restrict__ Cl,
          const float* __restrict__ biasM, const float* __restrict__ biasN,
          const float* __restrict__ resid, float scale)
{
    extern __shared__ char dsm[];
    const uint32_t sbase = (smem_u32(dsm) + 127u) & ~127u;
    const int tid = threadIdx.x, lane = tid & 31, wid = tid >> 5;
    const int warpM = (wid & 3) * 32, warpN = (wid >> 2) * 64;
    const int bz = blockIdx.z;
    Ah += (size_t)bz * sA;  Al += (size_t)bz * sA;
    Bh += (size_t)bz * sB;  Bl += (size_t)bz * sB;
    if (Cf)    Cf    += (size_t)bz * sC;
    if (Ch)  { Ch    += (size_t)bz * sC; Cl += (size_t)bz * sC; }
    if (resid) resid += (size_t)bz * sC;
    const int m0 = blockIdx.y * 128, n0 = blockIdx.x * 128;
    const int niter = K >> 6;

    const int c_row = tid >> 3;
    const int c_seg = tid & 7;

    auto issue = [&](int kt){
        const int kk = kt * 64;
        const uint32_t sb = sbase + (kt % NSTAGE) * STG_B;
        #pragma unroll
        for (int j = 0; j < 16; j++){
            const int buf = j >> 2;
            const int row = c_row + ((j & 3) << 5);
            const int seg = c_seg;
            const __nv_bfloat16* gp;
            if      (buf == 0) gp = Ah + (size_t)(m0 + row) * K + kk + seg * 8;
            else if (buf == 1) gp = Al + (size_t)(m0 + row) * K + kk + seg * 8;
            else if (buf == 2) gp = Bh + (size_t)(n0 + row) * K + kk + seg * 8;
            else               gp = Bl + (size_t)(n0 + row) * K + kk + seg * 8;
            const uint32_t c = (uint32_t)((seg * 16) ^ ((row & 7) << 4));
            cp16(sb + buf * BUF_B + row * 128 + c, gp);
        }
        CP_COMMIT();
    };

    float acc[2][8][4];
    #pragma unroll
    for (int i = 0; i < 2; i++)
        #pragma unroll
        for (int j = 0; j < 8; j++)
            #pragma unroll
            for (int t = 0; t < 4; t++) acc[i][j][t] = 0.f;

    // ldmatrix lane addressing
    const int aRow = warpM + (lane & 15);
    const uint32_t aSz = (uint32_t)((aRow & 7) << 4);
    const uint32_t aC  = (uint32_t)((lane >> 4) << 4);
    const uint32_t aB0 = (uint32_t)(aRow * 128);
    const int bRow = warpN + ((lane >> 4) << 3) + (lane & 7);
    const uint32_t bSz = (uint32_t)((bRow & 7) << 4);
    const uint32_t bC  = (uint32_t)(((lane >> 3) & 1) << 4);
    const uint32_t bB0 = (uint32_t)(bRow * 128);

    // double-buffered fragments (pb = ko & 1)
    uint32_t a_h[2][2][4], a_l[2][2][4], b_h[2][4][4], b_l[2][4][4];

    issue(0); if (niter > 1) issue(1);

    for (int kt = 0; kt < niter; kt++){
        if (kt + 1 < niter) CP_WAIT1(); else CP_WAIT0();
        __syncthreads();
        if (kt + 2 < niter) issue(kt + 2);
        const uint32_t sb = sbase + (kt % NSTAGE) * STG_B;

        // preload fragments for ko = 0
        {
            const uint32_t kb = 0;
            #pragma unroll
            for (int mt = 0; mt < 2; mt++){
                uint32_t ad = sb + aB0 + (uint32_t)(mt * 16 * 128) + ((aC + kb) ^ aSz);
                LDX4(a_h[0][mt][0], a_h[0][mt][1], a_h[0][mt][2], a_h[0][mt][3], ad);
                LDX4(a_l[0][mt][0], a_l[0][mt][1], a_l[0][mt][2], a_l[0][mt][3], ad + BUF_B);
            }
            #pragma unroll
            for (int p = 0; p < 4; p++){
                uint32_t bd = sb + 2*BUF_B + bB0 + (uint32_t)(p * 16 * 128) + ((bC + kb) ^ bSz);
                LDX4(b_h[0][p][0], b_h[0][p][1], b_h[0][p][2], b_h[0][p][3], bd);
                LDX4(b_l[0][p][0], b_l[0][p][1], b_l[0][p][2], b_l[0][p][3], bd + BUF_B);
            }
        }

        #pragma unroll
        for (int ko = 0; ko < 4; ko++){
            const int pb = ko & 1, pn = pb ^ 1;
            if (ko < 3){   // prefetch fragments for ko+1 before this ko's MMAs
                const uint32_t kb = (uint32_t)((ko + 1) * 32);
                #pragma unroll
                for (int mt = 0; mt < 2; mt++){
                    uint32_t ad = sb + aB0 + (uint32_t)(mt * 16 * 128) + ((aC + kb) ^ aSz);
                    LDX4(a_h[pn][mt][0], a_h[pn][mt][1], a_h[pn][mt][2], a_h[pn][mt][3], ad);
                    LDX4(a_l[pn][mt][0], a_l[pn][mt][1], a_l[pn][mt][2], a_l[pn][mt][3], ad + BUF_B);
                }
                #pragma unroll
                for (int p = 0; p < 4; p++){
                    uint32_t bd = sb + 2*BUF_B + bB0 + (uint32_t)(p * 16 * 128) + ((bC + kb) ^ bSz);
                    LDX4(b_h[pn][p][0], b_h[pn][p][1], b_h[pn][p][2], b_h[pn][p][3], bd);
                    LDX4(b_l[pn][p][0], b_l[pn][p][1], b_l[pn][p][2], b_l[pn][p][3], bd + BUF_B);
                }
            }
            #pragma unroll
            for (int mt = 0; mt < 2; mt++)
                #pragma unroll
                for (int nt = 0; nt < 8; nt++){
                    uint32_t* bh = &b_h[pb][nt >> 1][(nt & 1) * 2];
                    uint32_t* bl = &b_l[pb][nt >> 1][(nt & 1) * 2];
                    MMA16816(acc[mt][nt], a_h[pb][mt], bh);
                    MMA16816(acc[mt][nt], a_h[pb][mt], bl);
                    MMA16816(acc[mt][nt], a_l[pb][mt], bh);
                }
        }
    }

    // ---- epilogue ----
    #pragma unroll
    for (int mt = 0; mt < 2; mt++){
        const int r0 = m0 + warpM + mt * 16 + (lane >> 2);
        const int r1 = r0 + 8;
        const float bm0 = biasM ? biasM[r0] : 0.f;
        const float bm1 = biasM ? biasM[r1] : 0.f;
        #pragma unroll
        for (int nt = 0; nt < 8; nt++){
            const int c = n0 + warpN + nt * 8 + ((lane & 3) << 1);
            float v0 = acc[mt][nt][0] * scale + bm0;
            float v1 = acc[mt][nt][1] * scale + bm0;
            float v2 = acc[mt][nt][2] * scale + bm1;
            float v3 = acc[mt][nt][3] * scale + bm1;
            if (biasN){
                float2 bn = *(const float2*)&biasN[c];
                v0 += bn.x; v1 += bn.y; v2 += bn.x; v3 += bn.y;
            }
            const size_t o0 = (size_t)r0 * ldc + c;
            const size_t o1 = (size_t)r1 * ldc + c;
            if (resid){
                float2 x0 = *(const float2*)&resid[o0];
                float2 x1 = *(const float2*)&resid[o1];
                v0 += x0.x; v1 += x0.y; v2 += x1.x; v3 += x1.y;
            }
            if (Cf){
                *(float2*)&Cf[o0] = make_float2(v0, v1);
                *(float2*)&Cf[o1] = make_float2(v2, v3);
            }
            if (Ch){
                uint32_t h01, l01, h23, l23;
                split2pack(v0, v1, h01, l01);
                split2pack(v2, v3, h23, l23);
                *(uint32_t*)&Ch[o0] = h01;  *(uint32_t*)&Cl[o0] = l01;
                *(uint32_t*)&Ch[o1] = h23;  *(uint32_t*)&Cl[o1] = l23;
            }
        }
    }
}

// ---------------- weight convert ----------------
__global__ void __launch_bounds__(256) wconv(const float* __restrict__ w0, const float* __restrict__ w1,
                                             const float* __restrict__ w2, const float* __restrict__ w3,
                                             __nv_bfloat16* __restrict__ hi, __nv_bfloat16* __restrict__ lo)
{
    int i = blockIdx.x * 256 + threadIdx.x;
    int w = i >> 16;
    int off = (i & 65535) * 4;
    const float* src = (w == 0) ? w0 : (w == 1) ? w1 : (w == 2) ? w2 : w3;
    float4 v = *(const float4*)(src + off);
    uint32_t h01, l01, h23, l23;
    split2pack(v.x, v.y, h01, l01);
    split2pack(v.z, v.w, h23, l23);
    size_t o = (size_t)w * CC * CC + off;
    *(uint32_t*)&hi[o]   = h01;  *(uint32_t*)&lo[o]   = l01;
    *(uint32_t*)&hi[o+2] = h23;  *(uint32_t*)&lo[o+2] = l23;
}

// ---------------- GroupNorm stats ----------------
__global__ void __launch_bounds__(1024) gn_stats(const float* __restrict__ x, float* __restrict__ stats)
{
    int b = blockIdx.x >> 3, g = blockIdx.x & 7;
    const float* xp = x + ((size_t)b*CC + (size_t)g*CPG) * LLEN;
    const int n = CPG * LLEN;
    int tid = threadIdx.x;
    float s = 0.f, ss = 0.f;
    for (int i = tid; i < n; i += 1024){ float v = xp[i]; s += v; ss += v*v; }
    __shared__ float rs[32], rss[32];
    #pragma unroll
    for (int o = 16; o; o >>= 1){
        s  += __shfl_xor_sync(0xffffffffu, s,  o);
        ss += __shfl_xor_sync(0xffffffffu, ss, o);
    }
    if ((tid & 31) == 0){ rs[tid>>5] = s; rss[tid>>5] = ss; }
    __syncthreads();
    if (tid == 0){
        float t = 0.f, t2 = 0.f;
        #pragma unroll
        for (int i = 0; i < 32; i++){ t += rs[i]; t2 += rss[i]; }
        float mean = t / (float)n;
        float var  = t2 / (float)n - mean*mean;
        stats[blockIdx.x*2]   = mean;
        stats[blockIdx.x*2+1] = rsqrtf(var + 1e-6f);
    }
}

// ---------------- GroupNorm apply + transpose -> hT hi/lo ----------------
__global__ void __launch_bounds__(256) gn_apply_t(const float* __restrict__ x,
                                                  const float* __restrict__ stats,
                                                  const float* __restrict__ gamma,
                                                  const float* __restrict__ beta,
                                                  __nv_bfloat16* __restrict__ hTh,
                                                  __nv_bfloat16* __restrict__ hTl)
{
    __shared__ float tile[64][33];
    int b = blockIdx.z, g = blockIdx.y, l0 = blockIdx.x * 32;
    float mean = stats[(b*NGRP+g)*2], inv = stats[(b*NGRP+g)*2+1];
    const float* xp = x + ((size_t)b*CC + (size_t)g*CPG) * LLEN;
    int tid = threadIdx.x;
    #pragma unroll
    for (int i = 0; i < 8; i++){
        int idx = tid + i*256; int c = idx >> 5, l = idx & 31;
        float v = xp[(size_t)c*LLEN + l0 + l];
        tile[c][l] = (v - mean) * inv * gamma[g*CPG + c] + beta[g*CPG + c];
    }
    __syncthreads();
    size_t base = (size_t)b * LLEN * CC;
    #pragma unroll
    for (int i = 0; i < 8; i++){
        int idx = tid + i*256; int l = idx >> 6, c = idx & 63;
        size_t o = base + (size_t)(l0 + l)*CC + g*CPG + c;
        split1(tile[c][l], &hTh[o], &hTl[o]);
    }
}

// ---------------- row softmax over bf16 hi/lo pair, in place ----------------
__global__ void __launch_bounds__(256) softmax_kernel(__nv_bfloat16* __restrict__ Sh,
                                                      __nv_bfloat16* __restrict__ Sl)
{
    size_t ob = (size_t)blockIdx.x * LLEN;
    int tid = threadIdx.x;
    float v[8];
    float mx = -1e30f;
    #pragma unroll
    for (int i = 0; i < 8; i++){
        int idx = tid + 256*i;
        v[i] = __bfloat162float(Sh[ob + idx]) + __bfloat162float(Sl[ob + idx]);
        mx = fmaxf(mx, v[i]);
    }
    __shared__ float rmax[8], rsum[8];
    #pragma unroll
    for (int o = 16; o; o >>= 1) mx = fmaxf(mx, __shfl_xor_sync(0xffffffffu, mx, o));
    if ((tid & 31) == 0) rmax[tid >> 5] = mx;
    __syncthreads();
    float m = rmax[0];
    #pragma unroll
    for (int i = 1; i < 8; i++) m = fmaxf(m, rmax[i]);
    float sm = 0.f;
    #pragma unroll
    for (int i = 0; i < 8; i++){ v[i] = __expf(v[i] - m); sm += v[i]; }
    #pragma unroll
    for (int o = 16; o; o >>= 1) sm += __shfl_xor_sync(0xffffffffu, sm, o);
    if ((tid & 31) == 0) rsum[tid >> 5] = sm;
    __syncthreads();
    float tot = 0.f;
    #pragma unroll
    for (int i = 0; i < 8; i++) tot += rsum[i];
    float inv = 1.f / tot;
    #pragma unroll
    for (int i = 0; i < 8; i++){
        int idx = tid + 256*i;
        split1(v[i] * inv, &Sh[ob + idx], &Sl[ob + idx]);
    }
}

// ---------------- launch ----------------
extern "C" void kernel_launch(void* const* d_in, const int* in_sizes, int n_in,
                              void* d_out, int out_size)
{
    const float* x     = (const float*)d_in[0];
    const float* gamma = (const float*)d_in[1];
    const float* beta  = (const float*)d_in[2];
    const float* wq    = (const float*)d_in[3];
    const float* bq    = (const float*)d_in[4];
    const float* wk    = (const float*)d_in[5];
    const float* bk    = (const float*)d_in[6];
    const float* wv    = (const float*)d_in[7];
    const float* bv    = (const float*)d_in[8];
    const float* wo    = (const float*)d_in[9];
    const float* bo    = (const float*)d_in[10];
    float* out = (float*)d_out;

    __nv_bfloat16 *hTh,*hTl,*qh,*ql,*kh,*kl,*vh,*vl,*h2h,*h2l,*sh,*sl,*wh,*wl;
    float *stats;
    cudaGetSymbolAddress((void**)&hTh, g_hTh); cudaGetSymbolAddress((void**)&hTl, g_hTl);
    cudaGetSymbolAddress((void**)&qh,  g_qh);  cudaGetSymbolAddress((void**)&ql,  g_ql);
    cudaGetSymbolAddress((void**)&kh,  g_kh);  cudaGetSymbolAddress((void**)&kl,  g_kl);
    cudaGetSymbolAddress((void**)&vh,  g_vh);  cudaGetSymbolAddress((void**)&vl,  g_vl);
    cudaGetSymbolAddress((void**)&h2h, g_h2h); cudaGetSymbolAddress((void**)&h2l, g_h2l);
    cudaGetSymbolAddress((void**)&sh,  g_sh);  cudaGetSymbolAddress((void**)&sl,  g_sl);
    cudaGetSymbolAddress((void**)&wh,  g_wh);  cudaGetSymbolAddress((void**)&wl,  g_wl);
    cudaGetSymbolAddress((void**)&stats, g_stats);

    cudaFuncSetAttribute(hmma_gemm, cudaFuncAttributeMaxDynamicSharedMemorySize, DYN_SMEM);

    const long LL = (long)LLEN * LLEN;
    const float scl = 1.0f / sqrtf((float)CC);

    gn_stats<<<BB*NGRP, 1024>>>(x, stats);
    wconv<<<1024, 256>>>(wq, wk, wv, wo, wh, wl);
    gn_apply_t<<<dim3(LLEN/32, NGRP, BB), 256>>>(x, stats, gamma, beta, hTh, hTl);

    dim3 blk(256);
    // qT[l,c] = sum hT[l,:]*wq[c,:] + bq[c]     M=L,N=C,K=C
    hmma_gemm<<<dim3(4,16,BB), blk, DYN_SMEM>>>(hTh, hTl, wh + 0*CC*CC, wl + 0*CC*CC,
        CC, CC, (long)CL, 0L, (long)CL, nullptr, qh, ql, nullptr, bq, nullptr, 1.f);
    hmma_gemm<<<dim3(4,16,BB), blk, DYN_SMEM>>>(hTh, hTl, wh + 1*CC*CC, wl + 1*CC*CC,
        CC, CC, (long)CL, 0L, (long)CL, nullptr, kh, kl, nullptr, bk, nullptr, 1.f);
    // v[c,l] = sum wv[c,:]*hT[l,:] + bv[c]      M=C,N=L,K=C
    hmma_gemm<<<dim3(16,4,BB), blk, DYN_SMEM>>>(wh + 2*CC*CC, wl + 2*CC*CC, hTh, hTl,
        CC, LLEN, 0L, (long)CL, (long)CL, nullptr, vh, vl, bv, nullptr, nullptr, 1.f);
    // S[i,j] = scl * sum qT[i,:]*kT[j,:]        M=L,N=L,K=C  -> bf16 hi/lo direct
    hmma_gemm<<<dim3(16,16,BB), blk, DYN_SMEM>>>(qh, ql, kh, kl,
        CC, LLEN, (long)CL, (long)CL, LL, nullptr, sh, sl, nullptr, nullptr, nullptr, scl);

    softmax_kernel<<<BB*LLEN, 256>>>(sh, sl);

    // h2T[i,c] = sum S[i,:]*v[c,:]              M=L,N=C,K=L
    hmma_gemm<<<dim3(4,16,BB), blk, DYN_SMEM>>>(sh, sl, vh, vl,
        LLEN, CC, LL, (long)CL, (long)CL, nullptr, h2h, h2l, nullptr, nullptr, nullptr, 1.f);
    // out[c,l] = x + sum wo[c,:]*h2T[l,:] + bo  M=C,N=L,K=C
    hmma_gemm<<<dim3(16,4,BB), blk, DYN_SMEM>>>(wh + 3*CC*CC, wl + 3*CC*CC, h2h, h2l,
        CC, LLEN, 0L, (long)CL, (long)CL, out, nullptr, nullptr, bo, nullptr, x, 1.f);
}

// round 6
// speedup vs baseline: 2.8094x; 1.0070x over previous
#include <cuda_runtime.h>
#include <cuda_bf16.h>
#include <cstdint>
#include <math.h>

#define BB 8
#define CC 512
#define LLEN 2048
#define NGRP 8
#define CPG 64
#define CL (CC*LLEN)

// ---------------- scratch ----------------
__device__ __nv_bfloat16 g_hTh[(size_t)BB*CL], g_hTl[(size_t)BB*CL];     // hT [B][L][C]
__device__ __nv_bfloat16 g_qkh[(size_t)BB*LLEN*1024], g_qkl[(size_t)BB*LLEN*1024]; // [B][L][1024] q|k
__device__ __nv_bfloat16 g_vh [(size_t)BB*CL], g_vl [(size_t)BB*CL];     // v  [B][C][L]
__device__ __nv_bfloat16 g_h2h[(size_t)BB*CL], g_h2l[(size_t)BB*CL];     // h2T[B][L][C]
__device__ __nv_bfloat16 g_sh [(size_t)BB*LLEN*LLEN], g_sl[(size_t)BB*LLEN*LLEN];
__device__ __nv_bfloat16 g_wh [4*CC*CC], g_wl[4*CC*CC];                  // wq,wk,wv,wo
__device__ float g_bqk[1024];
__device__ float g_stats[BB*NGRP*2];

// ---------------- helpers ----------------
__device__ __forceinline__ uint32_t smem_u32(const void* p){
    uint32_t a;
    asm("{ .reg .u64 t; cvta.to.shared.u64 t, %1; cvt.u32.u64 %0, t; }" : "=r"(a) : "l"(p));
    return a;
}
__device__ __forceinline__ void cp16(uint32_t s, const void* g){
    asm volatile("cp.async.cg.shared.global [%0], [%1], 16;" :: "r"(s), "l"(g));
}
#define CP_COMMIT() asm volatile("cp.async.commit_group;" ::: "memory")
#define CP_WAIT2()  asm volatile("cp.async.wait_group 2;" ::: "memory")
#define CP_WAIT1()  asm volatile("cp.async.wait_group 1;" ::: "memory")
#define CP_WAIT0()  asm volatile("cp.async.wait_group 0;" ::: "memory")

#define LDX4(r0,r1,r2,r3,addr) \
    asm volatile("ldmatrix.sync.aligned.m8n8.x4.shared.b16 {%0,%1,%2,%3}, [%4];" \
        : "=r"(r0), "=r"(r1), "=r"(r2), "=r"(r3) : "r"(addr))

#define MMA16816(d, a, b) \
    asm volatile("mma.sync.aligned.m16n8k16.row.col.f32.bf16.bf16.f32 " \
        "{%0,%1,%2,%3}, {%4,%5,%6,%7}, {%8,%9}, {%0,%1,%2,%3};" \
        : "+f"((d)[0]), "+f"((d)[1]), "+f"((d)[2]), "+f"((d)[3]) \
        : "r"((a)[0]), "r"((a)[1]), "r"((a)[2]), "r"((a)[3]), "r"((b)[0]), "r"((b)[1]))

__device__ __forceinline__ void split2pack(float v0, float v1, uint32_t& hi, uint32_t& lo){
    uint32_t u0 = __float_as_uint(v0) & 0xffff0000u;
    uint32_t u1 = __float_as_uint(v1) & 0xffff0000u;
    hi = (u0 >> 16) | u1;
    float r0 = v0 - __uint_as_float(u0);
    float r1 = v1 - __uint_as_float(u1);
    asm("cvt.rn.bf16x2.f32 %0, %1, %2;" : "=r"(lo) : "f"(r1), "f"(r0));
}
__device__ __forceinline__ void split1(float v, __nv_bfloat16* hp, __nv_bfloat16* lp){
    uint32_t u = __float_as_uint(v) & 0xffff0000u;
    *(unsigned short*)hp = (unsigned short)(u >> 16);
    *lp = __float2bfloat16(v - __uint_as_float(u));
}

// ---------------- HMMA GEMM: tile 256x128, 512 threads, BK=32, 4-stage ----------------
// D[M,N] = scale*sum_k A[m][k]*B[n][k] (+biasM)(+biasN)(+resid); rows K-contiguous w/ strides lda/ldb
#define OFF_AH 0
#define OFF_AL 16384
#define OFF_BH 32768
#define OFF_BL 40960
#define STG_B  49152
#define NSTAGE 4
#define DYN_SMEM (NSTAGE*STG_B + 128)

__global__ void __launch_bounds__(512, 1)
hmma_gemm(const __nv_bfloat16* __restrict__ Ah, const __nv_bfloat16* __restrict__ Al,
          const __nv_bfloat16* __restrict__ Bh, const __nv_bfloat16* __restrict__ Bl,
          int K, int lda, int ldb, int ldc, long sA, long sB, long sC,
          float* __restrict__ Cf, __nv_bfloat16* __restrict__ Ch, __nv_bfloat16* __restrict__ Cl,
          const float* __restrict__ biasM, const float* __restrict__ biasN,
          const float* __restrict__ resid, float scale)
{
    extern __shared__ char dsm[];
    const uint32_t sbase = (smem_u32(dsm) + 127u) & ~127u;
    const int tid = threadIdx.x, lane = tid & 31, wid = tid >> 5;
    const int warpM = (wid & 3) * 64, warpN = (wid >> 2) * 32;
    const int bz = blockIdx.z;
    Ah += (size_t)bz * sA;  Al += (size_t)bz * sA;
    Bh += (size_t)bz * sB;  Bl += (size_t)bz * sB;
    if (Cf)    Cf    += (size_t)bz * sC;
    if (Ch)  { Ch    += (size_t)bz * sC; Cl += (size_t)bz * sC; }
    if (resid) resid += (size_t)bz * sC;
    const int m0 = blockIdx.y * 256, n0 = blockIdx.x * 128;
    const int niter = K >> 5;

    // cp.async: 6 chunks/thread. row = tid>>2 (0..127), seg = tid&3 (16B each)
    const int c_row = tid >> 2, c_seg = tid & 3;
    const uint32_t c_sw0 = (uint32_t)((((c_row      ) >> 1) & 3) << 4);
    const uint32_t c_sw1 = (uint32_t)((((c_row + 128) >> 1) & 3) << 4);
    const uint32_t c_cb  = (uint32_t)(c_seg * 16);

    auto issue = [&](int kt){
        const int kk = kt * 32;
        const uint32_t sb = sbase + (kt & (NSTAGE-1)) * STG_B;
        const uint32_t d0 = sb + c_row * 64 + (c_cb ^ c_sw0);          // rows 0..127
        const uint32_t d1 = sb + (c_row + 128) * 64 + (c_cb ^ c_sw1);  // rows 128..255
        const size_t ga0 = (size_t)(m0 + c_row) * lda + kk + c_seg * 8;
        const size_t ga1 = (size_t)(m0 + c_row + 128) * lda + kk + c_seg * 8;
        const size_t gb  = (size_t)(n0 + c_row) * ldb + kk + c_seg * 8;
        cp16(d0 + OFF_AH, Ah + ga0);
        cp16(d1 + OFF_AH, Ah + ga1);
        cp16(d0 + OFF_AL, Al + ga0);
        cp16(d1 + OFF_AL, Al + ga1);
        cp16(d0 + OFF_BH, Bh + gb);
        cp16(d0 + OFF_BL, Bl + gb);
        CP_COMMIT();
    };

    float acc[4][4][4];
    #pragma unroll
    for (int i = 0; i < 4; i++)
        #pragma unroll
        for (int j = 0; j < 4; j++)
            #pragma unroll
            for (int t = 0; t < 4; t++) acc[i][j][t] = 0.f;

    // ldmatrix lane addressing (64B rows); swizzle invariant under +16 rows
    const int aRow0 = warpM + (lane & 15);
    const uint32_t aSw = (uint32_t)(((aRow0 >> 1) & 3) << 4);
    const uint32_t aC  = (uint32_t)((lane >> 4) << 4);
    const int bRow0 = warpN + ((lane >> 4) << 3) + (lane & 7);
    const uint32_t bSw = (uint32_t)(((bRow0 >> 1) & 3) << 4);
    const uint32_t bC  = (uint32_t)(((lane >> 3) & 1) << 4);

    issue(0); issue(1); issue(2);

    for (int kt = 0; kt < niter; kt++){
        if (kt + 2 < niter)      CP_WAIT2();
        else if (kt + 1 < niter) CP_WAIT1();
        else                     CP_WAIT0();
        __syncthreads();
        if (kt + 3 < niter) issue(kt + 3);
        const uint32_t sb = sbase + (kt & (NSTAGE-1)) * STG_B;

        #pragma unroll
        for (int ko = 0; ko < 2; ko++){
            const uint32_t kb = (uint32_t)(ko * 32);
            uint32_t a_h[4][4], a_l[4][4], b_h[2][4], b_l[2][4];
            #pragma unroll
            for (int p = 0; p < 2; p++){
                uint32_t bd = sb + (uint32_t)((bRow0 + p*16) * 64) + ((kb + bC) ^ bSw);
                LDX4(b_h[p][0], b_h[p][1], b_h[p][2], b_h[p][3], bd + OFF_BH);
                LDX4(b_l[p][0], b_l[p][1], b_l[p][2], b_l[p][3], bd + OFF_BL);
            }
            #pragma unroll
            for (int mt = 0; mt < 4; mt++){
                uint32_t ad = sb + (uint32_t)((aRow0 + mt*16) * 64) + ((kb + aC) ^ aSw);
                LDX4(a_h[mt][0], a_h[mt][1], a_h[mt][2], a_h[mt][3], ad + OFF_AH);
                LDX4(a_l[mt][0], a_l[mt][1], a_l[mt][2], a_l[mt][3], ad + OFF_AL);
            }
            #pragma unroll
            for (int mt = 0; mt < 4; mt++)
                #pragma unroll
                for (int nt = 0; nt < 4; nt++){
                    uint32_t* bh = &b_h[nt >> 1][(nt & 1) * 2];
                    uint32_t* bl = &b_l[nt >> 1][(nt & 1) * 2];
                    MMA16816(acc[mt][nt], a_h[mt], bh);
                    MMA16816(acc[mt][nt], a_h[mt], bl);
                    MMA16816(acc[mt][nt], a_l[mt], bh);
                }
        }
    }

    // ---- epilogue ----
    #pragma unroll
    for (int mt = 0; mt < 4; mt++){
        const int r0 = m0 + warpM + mt * 16 + (lane >> 2);
        const int r1 = r0 + 8;
        const float bm0 = biasM ? biasM[r0] : 0.f;
        const float bm1 = biasM ? biasM[r1] : 0.f;
        #pragma unroll
        for (int nt = 0; nt < 4; nt++){
            const int c = n0 + warpN + nt * 8 + ((lane & 3) << 1);
            float v0 = acc[mt][nt][0] * scale + bm0;
            float v1 = acc[mt][nt][1] * scale + bm0;
            float v2 = acc[mt][nt][2] * scale + bm1;
            float v3 = acc[mt][nt][3] * scale + bm1;
            if (biasN){
                float2 bn = *(const float2*)&biasN[c];
                v0 += bn.x; v1 += bn.y; v2 += bn.x; v3 += bn.y;
            }
            const size_t o0 = (size_t)r0 * ldc + c;
            const size_t o1 = (size_t)r1 * ldc + c;
            if (resid){
                float2 x0 = *(const float2*)&resid[o0];
                float2 x1 = *(const float2*)&resid[o1];
                v0 += x0.x; v1 += x0.y; v2 += x1.x; v3 += x1.y;
            }
            if (Cf){
                *(float2*)&Cf[o0] = make_float2(v0, v1);
                *(float2*)&Cf[o1] = make_float2(v2, v3);
            }
            if (Ch){
                uint32_t h01, l01, h23, l23;
                split2pack(v0, v1, h01, l01);
                split2pack(v2, v3, h23, l23);
                *(uint32_t*)&Ch[o0] = h01;  *(uint32_t*)&Cl[o0] = l01;
                *(uint32_t*)&Ch[o1] = h23;  *(uint32_t*)&Cl[o1] = l23;
            }
        }
    }
}

// ---------------- weight convert ----------------
__global__ void __launch_bounds__(256) wconv(const float* __restrict__ w0, const float* __restrict__ w1,
                                             const float* __restrict__ w2, const float* __restrict__ w3,
                                             __nv_bfloat16* __restrict__ hi, __nv_bfloat16* __restrict__ lo)
{
    int i = blockIdx.x * 256 + threadIdx.x;
    int w = i >> 16;
    int off = (i & 65535) * 4;
    const float* src = (w == 0) ? w0 : (w == 1) ? w1 : (w == 2) ? w2 : w3;
    float4 v = *(const float4*)(src + off);
    uint32_t h01, l01, h23, l23;
    split2pack(v.x, v.y, h01, l01);
    split2pack(v.z, v.w, h23, l23);
    size_t o = (size_t)w * CC * CC + off;
    *(uint32_t*)&hi[o]   = h01;  *(uint32_t*)&lo[o]   = l01;
    *(uint32_t*)&hi[o+2] = h23;  *(uint32_t*)&lo[o+2] = l23;
}

__global__ void bcat(const float* __restrict__ bq, const float* __restrict__ bk,
                     float* __restrict__ o)
{
    int i = blockIdx.x * 256 + threadIdx.x;
    if (i < 512) o[i] = bq[i];
    else if (i < 1024) o[i] = bk[i - 512];
}

// ---------------- GroupNorm stats ----------------
__global__ void __launch_bounds__(1024) gn_stats(const float* __restrict__ x, float* __restrict__ stats)
{
    int b = blockIdx.x >> 3, g = blockIdx.x & 7;
    const float* xp = x + ((size_t)b*CC + (size_t)g*CPG) * LLEN;
    const int n = CPG * LLEN;
    int tid = threadIdx.x;
    float s = 0.f, ss = 0.f;
    for (int i = tid; i < n; i += 1024){ float v = xp[i]; s += v; ss += v*v; }
    __shared__ float rs[32], rss[32];
    #pragma unroll
    for (int o = 16; o; o >>= 1){
        s  += __shfl_xor_sync(0xffffffffu, s,  o);
        ss += __shfl_xor_sync(0xffffffffu, ss, o);
    }
    if ((tid & 31) == 0){ rs[tid>>5] = s; rss[tid>>5] = ss; }
    __syncthreads();
    if (tid == 0){
        float t = 0.f, t2 = 0.f;
        #pragma unroll
        for (int i = 0; i < 32; i++){ t += rs[i]; t2 += rss[i]; }
        float mean = t / (float)n;
        float var  = t2 / (float)n - mean*mean;
        stats[blockIdx.x*2]   = mean;
        stats[blockIdx.x*2+1] = rsqrtf(var + 1e-6f);
    }
}

// ---------------- GroupNorm apply + transpose -> hT hi/lo ----------------
__global__ void __launch_bounds__(256) gn_apply_t(const float* __restrict__ x,
                                                  const float* __restrict__ stats,
                                                  const float* __restrict__ gamma,
                                                  const float* __restrict__ beta,
                                                  __nv_bfloat16* __restrict__ hTh,
                                                  __nv_bfloat16* __restrict__ hTl)
{
    __shared__ float tile[64][33];
    int b = blockIdx.z, g = blockIdx.y, l0 = blockIdx.x * 32;
    float mean = stats[(b*NGRP+g)*2], inv = stats[(b*NGRP+g)*2+1];
    const float* xp = x + ((size_t)b*CC + (size_t)g*CPG) * LLEN;
    int tid = threadIdx.x;
    #pragma unroll
    for (int i = 0; i < 8; i++){
        int idx = tid + i*256; int c = idx >> 5, l = idx & 31;
        float v = xp[(size_t)c*LLEN + l0 + l];
        tile[c][l] = (v - mean) * inv * gamma[g*CPG + c] + beta[g*CPG + c];
    }
    __syncthreads();
    size_t base = (size_t)b * LLEN * CC;
    #pragma unroll
    for (int i = 0; i < 8; i++){
        int idx = tid + i*256; int l = idx >> 6, c = idx & 63;
        size_t o = base + (size_t)(l0 + l)*CC + g*CPG + c;
        split1(tile[c][l], &hTh[o], &hTl[o]);
    }
}

// ---------------- row softmax over bf16 hi/lo pair, vectorized ----------------
__global__ void __launch_bounds__(256) softmax_kernel(__nv_bfloat16* __restrict__ Sh,
                                                      __nv_bfloat16* __restrict__ Sl)
{
    size_t ob = (size_t)blockIdx.x * LLEN;
    int tid = threadIdx.x;
    int base = tid * 8;
    uint4 hv = *(uint4*)&Sh[ob + base];
    uint4 lv = *(uint4*)&Sl[ob + base];
    float v[8];
    {
        uint32_t hw[4] = {hv.x, hv.y, hv.z, hv.w};
        uint32_t lw[4] = {lv.x, lv.y, lv.z, lv.w};
        #pragma unroll
        for (int i = 0; i < 4; i++){
            v[2*i]   = __uint_as_float(hw[i] << 16)          + __uint_as_float(lw[i] << 16);
            v[2*i+1] = __uint_as_float(hw[i] & 0xffff0000u)  + __uint_as_float(lw[i] & 0xffff0000u);
        }
    }
    float mx = -1e30f;
    #pragma unroll
    for (int i = 0; i < 8; i++) mx = fmaxf(mx, v[i]);
    __shared__ float rmax[8], rsum[8];
    #pragma unroll
    for (int o = 16; o; o >>= 1) mx = fmaxf(mx, __shfl_xor_sync(0xffffffffu, mx, o));
    if ((tid & 31) == 0) rmax[tid >> 5] = mx;
    __syncthreads();
    float m = rmax[0];
    #pragma unroll
    for (int i = 1; i < 8; i++) m = fmaxf(m, rmax[i]);
    float sm = 0.f;
    #pragma unroll
    for (int i = 0; i < 8; i++){ v[i] = __expf(v[i] - m); sm += v[i]; }
    #pragma unroll
    for (int o = 16; o; o >>= 1) sm += __shfl_xor_sync(0xffffffffu, sm, o);
    if ((tid & 31) == 0) rsum[tid >> 5] = sm;
    __syncthreads();
    float tot = 0.f;
    #pragma unroll
    for (int i = 0; i < 8; i++) tot += rsum[i];
    float inv = 1.f / tot;
    uint32_t ho[4], lo[4];
    #pragma unroll
    for (int i = 0; i < 4; i++)
        split2pack(v[2*i] * inv, v[2*i+1] * inv, ho[i], lo[i]);
    *(uint4*)&Sh[ob + base] = make_uint4(ho[0], ho[1], ho[2], ho[3]);
    *(uint4*)&Sl[ob + base] = make_uint4(lo[0], lo[1], lo[2], lo[3]);
}

// ---------------- launch ----------------
extern "C" void kernel_launch(void* const* d_in, const int* in_sizes, int n_in,
                              void* d_out, int out_size)
{
    const float* x     = (const float*)d_in[0];
    const float* gamma = (const float*)d_in[1];
    const float* beta  = (const float*)d_in[2];
    const float* wq    = (const float*)d_in[3];
    const float* bq    = (const float*)d_in[4];
    const float* wk    = (const float*)d_in[5];
    const float* bk    = (const float*)d_in[6];
    const float* wv    = (const float*)d_in[7];
    const float* bv    = (const float*)d_in[8];
    const float* wo    = (const float*)d_in[9];
    const float* bo    = (const float*)d_in[10];
    float* out = (float*)d_out;

    __nv_bfloat16 *hTh,*hTl,*qkh,*qkl,*vh,*vl,*h2h,*h2l,*sh,*sl,*wh,*wl;
    float *stats, *bqk;
    cudaGetSymbolAddress((void**)&hTh, g_hTh); cudaGetSymbolAddress((void**)&hTl, g_hTl);
    cudaGetSymbolAddress((void**)&qkh, g_qkh); cudaGetSymbolAddress((void**)&qkl, g_qkl);
    cudaGetSymbolAddress((void**)&vh,  g_vh);  cudaGetSymbolAddress((void**)&vl,  g_vl);
    cudaGetSymbolAddress((void**)&h2h, g_h2h); cudaGetSymbolAddress((void**)&h2l, g_h2l);
    cudaGetSymbolAddress((void**)&sh,  g_sh);  cudaGetSymbolAddress((void**)&sl,  g_sl);
    cudaGetSymbolAddress((void**)&wh,  g_wh);  cudaGetSymbolAddress((void**)&wl,  g_wl);
    cudaGetSymbolAddress((void**)&stats, g_stats);
    cudaGetSymbolAddress((void**)&bqk, g_bqk);

    cudaFuncSetAttribute(hmma_gemm, cudaFuncAttributeMaxDynamicSharedMemorySize, DYN_SMEM);

    const long LL  = (long)LLEN * LLEN;
    const long LQK = (long)LLEN * 1024;
    const float scl = 1.0f / sqrtf((float)CC);

    gn_stats<<<BB*NGRP, 1024>>>(x, stats);
    wconv<<<1024, 256>>>(wq, wk, wv, wo, wh, wl);
    bcat<<<4, 256>>>(bq, bk, bqk);
    gn_apply_t<<<dim3(LLEN/32, NGRP, BB), 256>>>(x, stats, gamma, beta, hTh, hTl);

    dim3 blk(512);
    // qk[l,n] = sum hT[l,:]*w_qk[n,:] + bqk[n]   M=L=2048, N=1024, K=512
    hmma_gemm<<<dim3(8,8,BB), blk, DYN_SMEM>>>(hTh, hTl, wh, wl,
        CC, CC, CC, 1024, (long)CL, 0L, LQK, nullptr, qkh, qkl, nullptr, bqk, nullptr, 1.f);
    // v[c,l] = sum wv[c,:]*hT[l,:] + bv[c]       M=512, N=2048, K=512
    hmma_gemm<<<dim3(16,2,BB), blk, DYN_SMEM>>>(wh + 2*CC*CC, wl + 2*CC*CC, hTh, hTl,
        CC, CC, CC, LLEN, 0L, (long)CL, (long)CL, nullptr, vh, vl, bv, nullptr, nullptr, 1.f);
    // S[i,j] = scl * sum q[i,:]*k[j,:]           M=N=2048, K=512 (q=qk[:,0:512], k=qk[:,512:1024])
    hmma_gemm<<<dim3(16,8,BB), blk, DYN_SMEM>>>(qkh, qkl, qkh + 512, qkl + 512,
        CC, 1024, 1024, LLEN, LQK, LQK, LL, nullptr, sh, sl, nullptr, nullptr, nullptr, scl);

    softmax_kernel<<<BB*LLEN, 256>>>(sh, sl);

    // h2T[i,c] = sum S[i,:]*v[c,:]               M=2048, N=512, K=2048
    hmma_gemm<<<dim3(4,8,BB), blk, DYN_SMEM>>>(sh, sl, vh, vl,
        LLEN, LLEN, LLEN, CC, LL, (long)CL, (long)CL, nullptr, h2h, h2l, nullptr, nullptr, nullptr, 1.f);
    // out[c,l] = x + sum wo[c,:]*h2T[l,:] + bo   M=512, N=2048, K=512
    hmma_gemm<<<dim3(16,2,BB), blk, DYN_SMEM>>>(wh + 3*CC*CC, wl + 3*CC*CC, h2h, h2l,
        CC, CC, CC, LLEN, 0L, (long)CL, (long)CL, out, nullptr, nullptr, bo, nullptr, x, 1.f);
}